// round 1
// baseline (speedup 1.0000x reference)
#include <cuda_runtime.h>
#include <math.h>

#define EMB   768
#define NH    12
#define HD    64
#define BATCH 8
#define SEQ   1024
#define MROWS (BATCH * SEQ)      // 8192
#define QKVN  (3 * EMB)          // 2304

// Scratch (no allocations allowed): qkv = 75.5 MB, att = 25 MB
__device__ float g_qkv[(size_t)MROWS * QKVN];
__device__ float g_att[(size_t)MROWS * EMB];

// ---------------------------------------------------------------------------
// SGEMM with fused bias: C[M,N] = A[M,K] @ B[K,N] + bias[N]
// 128x128 tile, BK=8, 256 threads, each thread computes 8x8.
// All dims here are multiples of the tile sizes (M=8192, N in {2304,768}, K=768),
// so no bounds checks.
// ---------------------------------------------------------------------------
__global__ __launch_bounds__(256) void sgemm_bias(
    const float* __restrict__ A, const float* __restrict__ B,
    const float* __restrict__ bias, float* __restrict__ C,
    int M, int N, int K)
{
    __shared__ float As[8][128];
    __shared__ float Bs[8][128];

    const int tid = threadIdx.x;
    const int tc  = tid & 15;          // 0..15 (column group)
    const int tr  = tid >> 4;          // 0..15 (row group)
    const int bm  = blockIdx.y;
    const int bn  = blockIdx.x;

    const float* Ab = A + (size_t)bm * 128 * K;
    const float* Bb = B + (size_t)bn * 128;

    const int aRow = tid >> 1;         // 0..127
    const int aCol = (tid & 1) * 4;    // 0 or 4
    const int bRow = tid >> 5;         // 0..7
    const int bCol = (tid & 31) * 4;   // 0..124

    float acc[8][8];
#pragma unroll
    for (int i = 0; i < 8; i++)
#pragma unroll
        for (int j = 0; j < 8; j++) acc[i][j] = 0.0f;

    for (int k0 = 0; k0 < K; k0 += 8) {
        float4 av = *(const float4*)(Ab + (size_t)aRow * K + k0 + aCol);
        float4 bv = *(const float4*)(Bb + (size_t)(k0 + bRow) * N + bCol);
        As[aCol + 0][aRow] = av.x;
        As[aCol + 1][aRow] = av.y;
        As[aCol + 2][aRow] = av.z;
        As[aCol + 3][aRow] = av.w;
        *(float4*)&Bs[bRow][bCol] = bv;
        __syncthreads();

#pragma unroll
        for (int k = 0; k < 8; k++) {
            float ra[8], rb[8];
            *(float4*)(ra)     = *(const float4*)&As[k][tr * 8];
            *(float4*)(ra + 4) = *(const float4*)&As[k][tr * 8 + 4];
            *(float4*)(rb)     = *(const float4*)&Bs[k][tc * 8];
            *(float4*)(rb + 4) = *(const float4*)&Bs[k][tc * 8 + 4];
#pragma unroll
            for (int i = 0; i < 8; i++)
#pragma unroll
                for (int j = 0; j < 8; j++)
                    acc[i][j] = fmaf(ra[i], rb[j], acc[i][j]);
        }
        __syncthreads();
    }

    // Epilogue: add bias, vectorized stores
    const int colBase = bn * 128 + tc * 8;
    float bb[8];
    *(float4*)(bb)     = *(const float4*)(bias + colBase);
    *(float4*)(bb + 4) = *(const float4*)(bias + colBase + 4);
#pragma unroll
    for (int i = 0; i < 8; i++) {
        size_t row = (size_t)bm * 128 + tr * 8 + i;
        float* Crow = C + row * N + colBase;
        float4 o0, o1;
        o0.x = acc[i][0] + bb[0]; o0.y = acc[i][1] + bb[1];
        o0.z = acc[i][2] + bb[2]; o0.w = acc[i][3] + bb[3];
        o1.x = acc[i][4] + bb[4]; o1.y = acc[i][5] + bb[5];
        o1.z = acc[i][6] + bb[6]; o1.w = acc[i][7] + bb[7];
        *(float4*)(Crow)     = o0;
        *(float4*)(Crow + 4) = o1;
    }
}

// ---------------------------------------------------------------------------
// Causal flash attention, fp32, one thread per query row.
// Block = 128 threads = 128 query rows of one (b,h). K/V tiles of 64 keys
// staged in smem, online softmax in chunks of 16 keys.
// qkv layout: [b*SEQ + t, 2304] with q at +0, k at +768, v at +1536, per head +h*64.
// out: g_att[(b*SEQ+t)*768 + h*64 + d]  (i.e. [B,T,H,d] = [M, 768])
// ---------------------------------------------------------------------------
__global__ __launch_bounds__(128) void flash_attn(
    const float* __restrict__ qkv, float* __restrict__ out)
{
    __shared__ float Ks[64 * 64];
    __shared__ float Vs[64 * 64];

    const int qt  = blockIdx.x;        // 0..7  (q tile of 128)
    const int h   = blockIdx.y;        // 0..11
    const int b   = blockIdx.z;        // 0..7
    const int tid = threadIdx.x;       // 0..127
    const int t   = qt * 128 + tid;    // query index

    // Load own q row, pre-scaled by 1/sqrt(64)
    float4 q4[16];
    {
        const float* qrow = qkv + ((size_t)(b * SEQ + t)) * QKVN + h * HD;
#pragma unroll
        for (int u = 0; u < 16; u++) {
            float4 v = *(const float4*)(qrow + u * 4);
            v.x *= 0.125f; v.y *= 0.125f; v.z *= 0.125f; v.w *= 0.125f;
            q4[u] = v;
        }
    }

    float o[64];
#pragma unroll
    for (int d = 0; d < 64; d++) o[d] = 0.0f;
    float m = -1e30f, l = 0.0f;

    const int n_kt = 2 * qt + 2;       // causal: key tiles covering <= qt*128+127

    for (int kt = 0; kt < n_kt; kt++) {
        __syncthreads();
        // cooperative load of K,V tiles (64 keys x 64 dims)
        const float* Kbase = qkv + ((size_t)(b * SEQ + kt * 64)) * QKVN + EMB + h * HD;
        const float* Vbase = Kbase + EMB;
#pragma unroll
        for (int j = 0; j < 8; j++) {
            int f   = tid + 128 * j;   // 0..1023 float4 index
            int row = f >> 4;
            int c4  = (f & 15) * 4;
            *(float4*)&Ks[row * 64 + c4] = *(const float4*)(Kbase + (size_t)row * QKVN + c4);
            *(float4*)&Vs[row * 64 + c4] = *(const float4*)(Vbase + (size_t)row * QKVN + c4);
        }
        __syncthreads();

        // process 4 chunks of 16 keys
        for (int c = 0; c < 4; c++) {
            const int kg0 = kt * 64 + c * 16;
            if (kg0 > t) break;        // fully masked from here on

            float s[16];
#pragma unroll
            for (int kk = 0; kk < 16; kk++) {
                const int kg = kg0 + kk;
                const float4* kr = (const float4*)(Ks + (c * 16 + kk) * 64);
                float a0 = 0.f, a1 = 0.f, a2 = 0.f, a3 = 0.f;
#pragma unroll
                for (int u = 0; u < 16; u++) {
                    float4 kv = kr[u];
                    a0 = fmaf(q4[u].x, kv.x, a0);
                    a1 = fmaf(q4[u].y, kv.y, a1);
                    a2 = fmaf(q4[u].z, kv.z, a2);
                    a3 = fmaf(q4[u].w, kv.w, a3);
                }
                s[kk] = (kg <= t) ? ((a0 + a1) + (a2 + a3)) : -1e30f;
            }

            float cmax = s[0];
#pragma unroll
            for (int kk = 1; kk < 16; kk++) cmax = fmaxf(cmax, s[kk]);

            if (cmax > m) {
                float corr = __expf(m - cmax);
                l *= corr;
#pragma unroll
                for (int d = 0; d < 64; d++) o[d] *= corr;
                m = cmax;
            }

#pragma unroll
            for (int kk = 0; kk < 16; kk++) {
                float p = __expf(s[kk] - m);
                l += p;
                const float4* vr = (const float4*)(Vs + (c * 16 + kk) * 64);
#pragma unroll
                for (int u = 0; u < 16; u++) {
                    float4 vv = vr[u];
                    o[4 * u + 0] = fmaf(p, vv.x, o[4 * u + 0]);
                    o[4 * u + 1] = fmaf(p, vv.y, o[4 * u + 1]);
                    o[4 * u + 2] = fmaf(p, vv.z, o[4 * u + 2]);
                    o[4 * u + 3] = fmaf(p, vv.w, o[4 * u + 3]);
                }
            }
        }
    }

    const float inv = 1.0f / l;
    float* orow = out + ((size_t)(b * SEQ + t)) * EMB + h * HD;
#pragma unroll
    for (int u = 0; u < 16; u++) {
        float4 v;
        v.x = o[4 * u + 0] * inv;
        v.y = o[4 * u + 1] * inv;
        v.z = o[4 * u + 2] * inv;
        v.w = o[4 * u + 3] * inv;
        *(float4*)(orow + 4 * u) = v;
    }
}

// ---------------------------------------------------------------------------
extern "C" void kernel_launch(void* const* d_in, const int* in_sizes, int n_in,
                              void* d_out, int out_size)
{
    (void)in_sizes; (void)n_in; (void)out_size;
    const float* x      = (const float*)d_in[0];
    const float* W_attn = (const float*)d_in[1];
    const float* b_attn = (const float*)d_in[2];
    const float* W_proj = (const float*)d_in[3];
    const float* b_proj = (const float*)d_in[4];
    float* out = (float*)d_out;

    float* qkv; float* att;
    cudaGetSymbolAddress((void**)&qkv, g_qkv);
    cudaGetSymbolAddress((void**)&att, g_att);

    // 1) qkv = x @ W_attn + b_attn   [8192 x 2304]
    sgemm_bias<<<dim3(QKVN / 128, MROWS / 128), 256>>>(x, W_attn, b_attn, qkv,
                                                       MROWS, QKVN, EMB);
    // 2) causal attention -> att [8192 x 768] ([B,T,H,d])
    flash_attn<<<dim3(SEQ / 128, NH, BATCH), 128>>>(qkv, att);

    // 3) out = att @ W_proj + b_proj  [8192 x 768]
    sgemm_bias<<<dim3(EMB / 128, MROWS / 128), 256>>>(att, W_proj, b_proj, out,
                                                      MROWS, EMB, EMB);
}

// round 6
// speedup vs baseline: 1.4254x; 1.4254x over previous
#include <cuda_runtime.h>
#include <cuda_bf16.h>
#include <cstdint>
#include <math.h>

#define EMB   768
#define NH    12
#define HD    64
#define BATCH 8
#define SEQ   1024
#define MROWS (BATCH * SEQ)      // 8192
#define QKVN  (3 * EMB)          // 2304

// ---------------------------------------------------------------------------
// Scratch (no allocations allowed)
// ---------------------------------------------------------------------------
__device__ __align__(256) float g_qkv[(size_t)MROWS * QKVN];          // 75.5 MB
__device__ __align__(256) float g_att[(size_t)MROWS * EMB];           // 25.2 MB
__device__ __align__(256) __nv_bfloat16 g_Ah[(size_t)MROWS * EMB];    // hi of x / att
__device__ __align__(256) __nv_bfloat16 g_Al[(size_t)MROWS * EMB];    // lo
__device__ __align__(256) __nv_bfloat16 g_WaTh[(size_t)QKVN * EMB];   // W_attn^T hi [N,K]
__device__ __align__(256) __nv_bfloat16 g_WaTl[(size_t)QKVN * EMB];
__device__ __align__(256) __nv_bfloat16 g_WpTh[(size_t)EMB * EMB];    // W_proj^T hi [N,K]
__device__ __align__(256) __nv_bfloat16 g_WpTl[(size_t)EMB * EMB];

// ---------------------------------------------------------------------------
// PTX helpers — ONLY sm_80+ features (no tcgen05: ptxas targets plain sm_103)
// ---------------------------------------------------------------------------
__device__ __forceinline__ uint32_t smem_u32(const void* p) {
    uint32_t a;
    asm("{ .reg .u64 t; cvta.to.shared.u64 t, %1; cvt.u32.u64 %0, t; }"
        : "=r"(a) : "l"(p));
    return a;
}

__device__ __forceinline__ void cp16(uint32_t dst, const void* src) {
    asm volatile("cp.async.cg.shared.global [%0], [%1], 16;"
                 :: "r"(dst), "l"(src) : "memory");
}
#define CP_COMMIT() asm volatile("cp.async.commit_group;" ::: "memory")
#define CP_WAIT(n)  asm volatile("cp.async.wait_group %0;" :: "n"(n) : "memory")

#define LDSM_X4(r0, r1, r2, r3, addr) \
    asm volatile("ldmatrix.sync.aligned.m8n8.x4.shared.b16 {%0,%1,%2,%3}, [%4];" \
                 : "=r"(r0), "=r"(r1), "=r"(r2), "=r"(r3) : "r"(addr))

__device__ __forceinline__ void mma16816(float* d,
                                         uint32_t a0, uint32_t a1, uint32_t a2, uint32_t a3,
                                         uint32_t b0, uint32_t b1) {
    asm volatile("mma.sync.aligned.m16n8k16.row.col.f32.bf16.bf16.f32 "
                 "{%0,%1,%2,%3}, {%4,%5,%6,%7}, {%8,%9}, {%0,%1,%2,%3};"
                 : "+f"(d[0]), "+f"(d[1]), "+f"(d[2]), "+f"(d[3])
                 : "r"(a0), "r"(a1), "r"(a2), "r"(a3), "r"(b0), "r"(b1));
}

// ---------------------------------------------------------------------------
// Split fp32 -> (hi, lo) bf16
// ---------------------------------------------------------------------------
__global__ __launch_bounds__(256) void split2(const float* __restrict__ src,
                                              __nv_bfloat16* __restrict__ hi,
                                              __nv_bfloat16* __restrict__ lo, int n)
{
    int i = blockIdx.x * blockDim.x + threadIdx.x;
    if (i < n) {
        float v = src[i];
        __nv_bfloat16 h = __float2bfloat16(v);
        hi[i] = h;
        lo[i] = __float2bfloat16(v - __bfloat162float(h));
    }
}

// Transpose + split: W [K,N] fp32 -> Th, Tl [N,K] bf16
__global__ __launch_bounds__(256) void transpose_split(
    const float* __restrict__ W, __nv_bfloat16* __restrict__ Th,
    __nv_bfloat16* __restrict__ Tl, int K, int N)
{
    __shared__ float t[32][33];
    int k0 = blockIdx.y * 32, n0 = blockIdx.x * 32;
#pragma unroll
    for (int r = 0; r < 32; r += 8) {
        int k = k0 + threadIdx.y + r;
        int n = n0 + threadIdx.x;
        t[threadIdx.y + r][threadIdx.x] = W[(size_t)k * N + n];
    }
    __syncthreads();
#pragma unroll
    for (int r = 0; r < 32; r += 8) {
        int n = n0 + threadIdx.y + r;
        int k = k0 + threadIdx.x;
        float v = t[threadIdx.x][threadIdx.y + r];
        __nv_bfloat16 h = __float2bfloat16(v);
        Th[(size_t)n * K + k] = h;
        Tl[(size_t)n * K + k] = __float2bfloat16(v - __bfloat162float(h));
    }
}

// ---------------------------------------------------------------------------
// mma.sync bf16 GEMM with split-3 scheme as K-concatenation.
// C[M,N] = A[M,768] @ B^T[N,768] + bias, computed as
//   AhBh + AlBh + AhBl  over 36 chunks of BK=64 (12 per term).
// CTA tile 128x128, 256 threads, 8 warps (4 along M x 2 along N),
// warp tile 32x64, m16n8k16 MMAs, SW128 XOR swizzle, 2-stage cp.async.
// Tiles: A/B [128 rows][64 bf16] = 128B-pitch rows; seg s (16B) stored at
// s ^ (row & 7)  -> conflict-free ldmatrix.
// ---------------------------------------------------------------------------
#define TILE_BYTES  (128 * 128)          // 16 KB (128 rows x 128B)
#define STAGE_BYTES (2 * TILE_BYTES)     // A + B
#define GEMM_SMEM   (2 * STAGE_BYTES + 1024)
#define NCHUNK      36

__device__ __forceinline__ void prefetch_tiles(
    uint32_t sA, uint32_t sB,
    const __nv_bfloat16* __restrict__ Asrc,
    const __nv_bfloat16* __restrict__ Bsrc, int tid)
{
#pragma unroll
    for (int j = 0; j < 4; j++) {
        int idx = tid + 256 * j;           // 0..1023
        int row = idx >> 3;                // 0..127
        int s   = idx & 7;                 // 0..7 (16B segment)
        cp16(sA + row * 128 + ((s ^ (row & 7)) << 4),
             Asrc + (size_t)row * EMB + s * 8);
    }
#pragma unroll
    for (int j = 0; j < 4; j++) {
        int idx = tid + 256 * j;
        int row = idx >> 3;
        int s   = idx & 7;
        cp16(sB + row * 128 + ((s ^ (row & 7)) << 4),
             Bsrc + (size_t)row * EMB + s * 8);
    }
}

__global__ __launch_bounds__(256) void gemm_mma(
    const __nv_bfloat16* __restrict__ Ah, const __nv_bfloat16* __restrict__ Al,
    const __nv_bfloat16* __restrict__ Bh, const __nv_bfloat16* __restrict__ Bl,
    const float* __restrict__ bias, float* __restrict__ C, int N)
{
    extern __shared__ char sm_raw[];
    const uint32_t base = (smem_u32(sm_raw) + 1023) & ~1023u;

    const int tid  = threadIdx.x;
    const int lane = tid & 31;
    const int w    = tid >> 5;
    const int wm   = w & 3;               // 0..3 (M direction, 32 rows each)
    const int wn   = w >> 2;              // 0..1 (N direction, 64 cols each)
    const int bn   = blockIdx.x;
    const int bm   = blockIdx.y;

    const size_t arow0 = (size_t)bm * 128;
    const size_t brow0 = (size_t)bn * 128;

    float acc[2][8][4];
#pragma unroll
    for (int mt = 0; mt < 2; mt++)
#pragma unroll
        for (int nt = 0; nt < 8; nt++)
#pragma unroll
            for (int e = 0; e < 4; e++) acc[mt][nt][e] = 0.0f;

    // chunk c -> source pointers + k offset
    auto chunk_src = [&](int c, const __nv_bfloat16*& As, const __nv_bfloat16*& Bs) {
        int koff;
        const __nv_bfloat16 *Ap, *Bp;
        if (c < 12)      { Ap = Ah; Bp = Bh; koff = c * 64; }
        else if (c < 24) { Ap = Al; Bp = Bh; koff = (c - 12) * 64; }
        else             { Ap = Ah; Bp = Bl; koff = (c - 24) * 64; }
        As = Ap + arow0 * EMB + koff;
        Bs = Bp + brow0 * EMB + koff;
    };

    // prefetch chunk 0 into stage 0
    {
        const __nv_bfloat16 *As, *Bs;
        chunk_src(0, As, Bs);
        prefetch_tiles(base, base + TILE_BYTES, As, Bs, tid);
        CP_COMMIT();
    }

    // ldmatrix per-lane address components (constant across chunks)
    const int q  = lane >> 3;             // matrix id 0..3
    const int r8 = lane & 7;              // row within 8x8 matrix

    for (int c = 0; c < NCHUNK; c++) {
        const uint32_t stA = base + (uint32_t)(c & 1) * STAGE_BYTES;
        const uint32_t stB = stA + TILE_BYTES;

        if (c + 1 < NCHUNK) {
            const __nv_bfloat16 *As, *Bs;
            chunk_src(c + 1, As, Bs);
            const uint32_t nA = base + (uint32_t)((c + 1) & 1) * STAGE_BYTES;
            prefetch_tiles(nA, nA + TILE_BYTES, As, Bs, tid);
            CP_COMMIT();
            CP_WAIT(1);                    // chunk c's group complete
        } else {
            CP_WAIT(0);
        }
        __syncthreads();

#pragma unroll
        for (int u = 0; u < 2; u++) {      // two k32 halves (k16 steps 2u, 2u+1)
            // A fragments: [mt][ksub][4 regs]
            uint32_t afr[2][2][4];
#pragma unroll
            for (int mt = 0; mt < 2; mt++)
#pragma unroll
                for (int ks = 0; ks < 2; ks++) {
                    int arow = wm * 32 + mt * 16 + (q & 1) * 8 + r8;
                    int aseg = (2 * u + ks) * 2 + (q >> 1);
                    uint32_t addr = stA + arow * 128 + ((aseg ^ (arow & 7)) << 4);
                    LDSM_X4(afr[mt][ks][0], afr[mt][ks][1],
                            afr[mt][ks][2], afr[mt][ks][3], addr);
                }
            // B: per n-tile one x4 covering both k16 steps of this half
#pragma unroll
            for (int nt = 0; nt < 8; nt++) {
                int brow = wn * 64 + nt * 8 + r8;
                int bseg = u * 4 + q;
                uint32_t addr = stB + brow * 128 + ((bseg ^ (brow & 7)) << 4);
                uint32_t t0, t1, t2, t3;   // (ks0 half0, ks0 half1, ks1 half0, ks1 half1)
                LDSM_X4(t0, t1, t2, t3, addr);
#pragma unroll
                for (int mt = 0; mt < 2; mt++) {
                    mma16816(acc[mt][nt], afr[mt][0][0], afr[mt][0][1],
                             afr[mt][0][2], afr[mt][0][3], t0, t1);
                    mma16816(acc[mt][nt], afr[mt][1][0], afr[mt][1][1],
                             afr[mt][1][2], afr[mt][1][3], t2, t3);
                }
            }
        }
        __syncthreads();
    }

    // Epilogue: D frag -> gmem with bias
    const int row0 = bm * 128 + wm * 32 + (lane >> 2);
    const int col0 = bn * 128 + wn * 64 + 2 * (lane & 3);
#pragma unroll
    for (int mt = 0; mt < 2; mt++)
#pragma unroll
        for (int nt = 0; nt < 8; nt++) {
            int rr = row0 + mt * 16;
            int cc = col0 + nt * 8;
            float b0 = bias[cc], b1 = bias[cc + 1];
            float2 v0 = make_float2(acc[mt][nt][0] + b0, acc[mt][nt][1] + b1);
            float2 v1 = make_float2(acc[mt][nt][2] + b0, acc[mt][nt][3] + b1);
            *(float2*)&C[(size_t)rr * N + cc]       = v0;
            *(float2*)&C[(size_t)(rr + 8) * N + cc] = v1;
        }
}

// ---------------------------------------------------------------------------
// Causal flash attention, fp32, one thread per query row (unchanged, verified)
// ---------------------------------------------------------------------------
__global__ __launch_bounds__(128) void flash_attn(
    const float* __restrict__ qkv, float* __restrict__ out)
{
    __shared__ float Ks[64 * 64];
    __shared__ float Vs[64 * 64];

    const int qt  = blockIdx.x;
    const int h   = blockIdx.y;
    const int b   = blockIdx.z;
    const int tid = threadIdx.x;
    const int t   = qt * 128 + tid;

    float4 q4[16];
    {
        const float* qrow = qkv + ((size_t)(b * SEQ + t)) * QKVN + h * HD;
#pragma unroll
        for (int u = 0; u < 16; u++) {
            float4 v = *(const float4*)(qrow + u * 4);
            v.x *= 0.125f; v.y *= 0.125f; v.z *= 0.125f; v.w *= 0.125f;
            q4[u] = v;
        }
    }

    float o[64];
#pragma unroll
    for (int d = 0; d < 64; d++) o[d] = 0.0f;
    float m = -1e30f, l = 0.0f;

    const int n_kt = 2 * qt + 2;

    for (int kt = 0; kt < n_kt; kt++) {
        __syncthreads();
        const float* Kbase = qkv + ((size_t)(b * SEQ + kt * 64)) * QKVN + EMB + h * HD;
        const float* Vbase = Kbase + EMB;
#pragma unroll
        for (int j = 0; j < 8; j++) {
            int f   = tid + 128 * j;
            int row = f >> 4;
            int c4  = (f & 15) * 4;
            *(float4*)&Ks[row * 64 + c4] = *(const float4*)(Kbase + (size_t)row * QKVN + c4);
            *(float4*)&Vs[row * 64 + c4] = *(const float4*)(Vbase + (size_t)row * QKVN + c4);
        }
        __syncthreads();

        for (int c = 0; c < 4; c++) {
            const int kg0 = kt * 64 + c * 16;
            if (kg0 > t) break;

            float s[16];
#pragma unroll
            for (int kk = 0; kk < 16; kk++) {
                const int kg = kg0 + kk;
                const float4* kr = (const float4*)(Ks + (c * 16 + kk) * 64);
                float a0 = 0.f, a1 = 0.f, a2 = 0.f, a3 = 0.f;
#pragma unroll
                for (int u = 0; u < 16; u++) {
                    float4 kv = kr[u];
                    a0 = fmaf(q4[u].x, kv.x, a0);
                    a1 = fmaf(q4[u].y, kv.y, a1);
                    a2 = fmaf(q4[u].z, kv.z, a2);
                    a3 = fmaf(q4[u].w, kv.w, a3);
                }
                s[kk] = (kg <= t) ? ((a0 + a1) + (a2 + a3)) : -1e30f;
            }

            float cmax = s[0];
#pragma unroll
            for (int kk = 1; kk < 16; kk++) cmax = fmaxf(cmax, s[kk]);

            if (cmax > m) {
                float corr = __expf(m - cmax);
                l *= corr;
#pragma unroll
                for (int d = 0; d < 64; d++) o[d] *= corr;
                m = cmax;
            }

#pragma unroll
            for (int kk = 0; kk < 16; kk++) {
                float p = __expf(s[kk] - m);
                l += p;
                const float4* vr = (const float4*)(Vs + (c * 16 + kk) * 64);
#pragma unroll
                for (int u = 0; u < 16; u++) {
                    float4 vv = vr[u];
                    o[4 * u + 0] = fmaf(p, vv.x, o[4 * u + 0]);
                    o[4 * u + 1] = fmaf(p, vv.y, o[4 * u + 1]);
                    o[4 * u + 2] = fmaf(p, vv.z, o[4 * u + 2]);
                    o[4 * u + 3] = fmaf(p, vv.w, o[4 * u + 3]);
                }
            }
        }
    }

    const float inv = 1.0f / l;
    float* orow = out + ((size_t)(b * SEQ + t)) * EMB + h * HD;
#pragma unroll
    for (int u = 0; u < 16; u++) {
        float4 v;
        v.x = o[4 * u + 0] * inv;
        v.y = o[4 * u + 1] * inv;
        v.z = o[4 * u + 2] * inv;
        v.w = o[4 * u + 3] * inv;
        *(float4*)(orow + 4 * u) = v;
    }
}

// ---------------------------------------------------------------------------
extern "C" void kernel_launch(void* const* d_in, const int* in_sizes, int n_in,
                              void* d_out, int out_size)
{
    (void)in_sizes; (void)n_in; (void)out_size;
    const float* x      = (const float*)d_in[0];
    const float* W_attn = (const float*)d_in[1];
    const float* b_attn = (const float*)d_in[2];
    const float* W_proj = (const float*)d_in[3];
    const float* b_proj = (const float*)d_in[4];
    float* out = (float*)d_out;

    float *qkv, *att;
    __nv_bfloat16 *ah, *al, *wath, *watl, *wpth, *wptl;
    cudaGetSymbolAddress((void**)&qkv, g_qkv);
    cudaGetSymbolAddress((void**)&att, g_att);
    cudaGetSymbolAddress((void**)&ah, g_Ah);
    cudaGetSymbolAddress((void**)&al, g_Al);
    cudaGetSymbolAddress((void**)&wath, g_WaTh);
    cudaGetSymbolAddress((void**)&watl, g_WaTl);
    cudaGetSymbolAddress((void**)&wpth, g_WpTh);
    cudaGetSymbolAddress((void**)&wptl, g_WpTl);

    cudaFuncSetAttribute(gemm_mma, cudaFuncAttributeMaxDynamicSharedMemorySize, GEMM_SMEM);

    // Split inputs / transpose+split weights to bf16 hi/lo
    {
        int n = MROWS * EMB;
        split2<<<(n + 255) / 256, 256>>>(x, ah, al, n);
    }
    transpose_split<<<dim3(QKVN / 32, EMB / 32), dim3(32, 8)>>>(W_attn, wath, watl, EMB, QKVN);
    transpose_split<<<dim3(EMB / 32, EMB / 32), dim3(32, 8)>>>(W_proj, wpth, wptl, EMB, EMB);

    // 1) qkv = x @ W_attn + b_attn   [8192 x 2304]
    gemm_mma<<<dim3(QKVN / 128, MROWS / 128), 256, GEMM_SMEM>>>(
        ah, al, wath, watl, b_attn, qkv, QKVN);

    // 2) causal attention -> att [8192 x 768]
    flash_attn<<<dim3(SEQ / 128, NH, BATCH), 128>>>(qkv, att);

    // 3) out = att @ W_proj + b_proj  [8192 x 768]
    {
        int n = MROWS * EMB;
        split2<<<(n + 255) / 256, 256>>>(att, ah, al, n);
    }
    gemm_mma<<<dim3(EMB / 128, MROWS / 128), 256, GEMM_SMEM>>>(
        ah, al, wpth, wptl, b_proj, out, EMB);
}

// round 7
// speedup vs baseline: 3.0257x; 2.1228x over previous
#include <cuda_runtime.h>
#include <cuda_bf16.h>
#include <cstdint>
#include <math.h>

#define EMB   768
#define NH    12
#define HD    64
#define BATCH 8
#define SEQ   1024
#define MROWS (BATCH * SEQ)      // 8192
#define QKVN  (3 * EMB)          // 2304

// 0.125 (1/sqrt(64)) * log2(e): folded into Q so softmax uses ex2
#define QSCALE 0.18033688011112042f

#define TSTRIDE ((size_t)BATCH * NH * SEQ * HD)   // 6291456 elems per tensor

// ---------------------------------------------------------------------------
// Scratch (no allocations allowed)
// ---------------------------------------------------------------------------
__device__ __align__(256) __nv_bfloat16 g_Ah[(size_t)MROWS * EMB];    // x / att hi
__device__ __align__(256) __nv_bfloat16 g_Al[(size_t)MROWS * EMB];    // lo
__device__ __align__(256) __nv_bfloat16 g_WaTh[(size_t)QKVN * EMB];
__device__ __align__(256) __nv_bfloat16 g_WaTl[(size_t)QKVN * EMB];
__device__ __align__(256) __nv_bfloat16 g_WpTh[(size_t)EMB * EMB];
__device__ __align__(256) __nv_bfloat16 g_WpTl[(size_t)EMB * EMB];
__device__ __align__(256) __nv_bfloat16 g_Sh[3 * TSTRIDE];            // q/k/v hi, head-major
__device__ __align__(256) __nv_bfloat16 g_Sl[3 * TSTRIDE];            // lo

// ---------------------------------------------------------------------------
// PTX helpers (sm_80-class only; toolchain targets plain sm_103)
// ---------------------------------------------------------------------------
__device__ __forceinline__ uint32_t smem_u32(const void* p) {
    uint32_t a;
    asm("{ .reg .u64 t; cvta.to.shared.u64 t, %1; cvt.u32.u64 %0, t; }"
        : "=r"(a) : "l"(p));
    return a;
}
__device__ __forceinline__ void cp16(uint32_t dst, const void* src) {
    asm volatile("cp.async.cg.shared.global [%0], [%1], 16;"
                 :: "r"(dst), "l"(src) : "memory");
}
#define CP_COMMIT() asm volatile("cp.async.commit_group;" ::: "memory")
#define CP_WAIT(n)  asm volatile("cp.async.wait_group %0;" :: "n"(n) : "memory")

#define LDSM_X4(r0, r1, r2, r3, addr) \
    asm volatile("ldmatrix.sync.aligned.m8n8.x4.shared.b16 {%0,%1,%2,%3}, [%4];" \
                 : "=r"(r0), "=r"(r1), "=r"(r2), "=r"(r3) : "r"(addr))
#define LDSM_X4T(r0, r1, r2, r3, addr) \
    asm volatile("ldmatrix.sync.aligned.m8n8.x4.trans.shared.b16 {%0,%1,%2,%3}, [%4];" \
                 : "=r"(r0), "=r"(r1), "=r"(r2), "=r"(r3) : "r"(addr))

__device__ __forceinline__ void mma16816(float* d,
                                         uint32_t a0, uint32_t a1, uint32_t a2, uint32_t a3,
                                         uint32_t b0, uint32_t b1) {
    asm volatile("mma.sync.aligned.m16n8k16.row.col.f32.bf16.bf16.f32 "
                 "{%0,%1,%2,%3}, {%4,%5,%6,%7}, {%8,%9}, {%0,%1,%2,%3};"
                 : "+f"(d[0]), "+f"(d[1]), "+f"(d[2]), "+f"(d[3])
                 : "r"(a0), "r"(a1), "r"(a2), "r"(a3), "r"(b0), "r"(b1));
}

__device__ __forceinline__ float ex2f(float x) {
    float y;
    asm("ex2.approx.ftz.f32 %0, %1;" : "=f"(y) : "f"(x));
    return y;
}
__device__ __forceinline__ uint32_t pack_bf2(__nv_bfloat16 lo, __nv_bfloat16 hi) {
    __nv_bfloat162 t = __halves2bfloat162(lo, hi);
    return *reinterpret_cast<uint32_t*>(&t);
}
// split two fp32 into packed hi-bf16x2 + residual-bf16x2
__device__ __forceinline__ void split_pack(float p0, float p1, uint32_t& hi, uint32_t& lo) {
    __nv_bfloat16 h0 = __float2bfloat16_rn(p0);
    __nv_bfloat16 h1 = __float2bfloat16_rn(p1);
    float r0 = p0 - __bfloat162float(h0);
    float r1 = p1 - __bfloat162float(h1);
    hi = pack_bf2(h0, h1);
    lo = pack_bf2(__float2bfloat16_rn(r0), __float2bfloat16_rn(r1));
}

// ---------------------------------------------------------------------------
// Split fp32 -> (hi, lo) bf16
// ---------------------------------------------------------------------------
__global__ __launch_bounds__(256) void split2(const float* __restrict__ src,
                                              __nv_bfloat16* __restrict__ hi,
                                              __nv_bfloat16* __restrict__ lo, int n)
{
    int i = blockIdx.x * blockDim.x + threadIdx.x;
    if (i < n) {
        float v = src[i];
        __nv_bfloat16 h = __float2bfloat16(v);
        hi[i] = h;
        lo[i] = __float2bfloat16(v - __bfloat162float(h));
    }
}

// Transpose + split: W [K,N] fp32 -> Th, Tl [N,K] bf16
__global__ __launch_bounds__(256) void transpose_split(
    const float* __restrict__ W, __nv_bfloat16* __restrict__ Th,
    __nv_bfloat16* __restrict__ Tl, int K, int N)
{
    __shared__ float t[32][33];
    int k0 = blockIdx.y * 32, n0 = blockIdx.x * 32;
#pragma unroll
    for (int r = 0; r < 32; r += 8) {
        int k = k0 + threadIdx.y + r;
        int n = n0 + threadIdx.x;
        t[threadIdx.y + r][threadIdx.x] = W[(size_t)k * N + n];
    }
    __syncthreads();
#pragma unroll
    for (int r = 0; r < 32; r += 8) {
        int n = n0 + threadIdx.y + r;
        int k = k0 + threadIdx.x;
        float v = t[threadIdx.x][threadIdx.y + r];
        __nv_bfloat16 h = __float2bfloat16(v);
        Th[(size_t)n * K + k] = h;
        Tl[(size_t)n * K + k] = __float2bfloat16(v - __bfloat162float(h));
    }
}

// ---------------------------------------------------------------------------
// mma.sync bf16 GEMM, split-3 over K-concatenation (validated in R6).
// MODE 0: C = A@B^T + bias (fp32 out).
// MODE 1: qkv epilogue — split result to bf16 hi/lo, scatter to head-major
//         [tensor][b*12+h][t][64], scaling q-columns by QSCALE.
// ---------------------------------------------------------------------------
#define TILE_BYTES  (128 * 128)
#define STAGE_BYTES (2 * TILE_BYTES)
#define GEMM_SMEM   (2 * STAGE_BYTES + 1024)
#define NCHUNK      36

__device__ __forceinline__ void prefetch_tiles(
    uint32_t sA, uint32_t sB,
    const __nv_bfloat16* __restrict__ Asrc,
    const __nv_bfloat16* __restrict__ Bsrc, int tid)
{
#pragma unroll
    for (int j = 0; j < 4; j++) {
        int idx = tid + 256 * j;
        int row = idx >> 3;
        int s   = idx & 7;
        cp16(sA + row * 128 + ((s ^ (row & 7)) << 4),
             Asrc + (size_t)row * EMB + s * 8);
    }
#pragma unroll
    for (int j = 0; j < 4; j++) {
        int idx = tid + 256 * j;
        int row = idx >> 3;
        int s   = idx & 7;
        cp16(sB + row * 128 + ((s ^ (row & 7)) << 4),
             Bsrc + (size_t)row * EMB + s * 8);
    }
}

template <int MODE>
__global__ __launch_bounds__(256) void gemm_mma(
    const __nv_bfloat16* __restrict__ Ah, const __nv_bfloat16* __restrict__ Al,
    const __nv_bfloat16* __restrict__ Bh, const __nv_bfloat16* __restrict__ Bl,
    const float* __restrict__ bias, float* __restrict__ C, int N,
    __nv_bfloat16* __restrict__ outh, __nv_bfloat16* __restrict__ outl)
{
    extern __shared__ char sm_raw[];
    const uint32_t base = (smem_u32(sm_raw) + 1023) & ~1023u;

    const int tid  = threadIdx.x;
    const int lane = tid & 31;
    const int w    = tid >> 5;
    const int wm   = w & 3;
    const int wn   = w >> 2;
    const int bn   = blockIdx.x;
    const int bm   = blockIdx.y;

    const size_t arow0 = (size_t)bm * 128;
    const size_t brow0 = (size_t)bn * 128;

    float acc[2][8][4];
#pragma unroll
    for (int mt = 0; mt < 2; mt++)
#pragma unroll
        for (int nt = 0; nt < 8; nt++)
#pragma unroll
            for (int e = 0; e < 4; e++) acc[mt][nt][e] = 0.0f;

    auto chunk_src = [&](int c, const __nv_bfloat16*& As, const __nv_bfloat16*& Bs) {
        int koff;
        const __nv_bfloat16 *Ap, *Bp;
        if (c < 12)      { Ap = Ah; Bp = Bh; koff = c * 64; }
        else if (c < 24) { Ap = Al; Bp = Bh; koff = (c - 12) * 64; }
        else             { Ap = Ah; Bp = Bl; koff = (c - 24) * 64; }
        As = Ap + arow0 * EMB + koff;
        Bs = Bp + brow0 * EMB + koff;
    };

    {
        const __nv_bfloat16 *As, *Bs;
        chunk_src(0, As, Bs);
        prefetch_tiles(base, base + TILE_BYTES, As, Bs, tid);
        CP_COMMIT();
    }

    const int q  = lane >> 3;
    const int r8 = lane & 7;

    for (int c = 0; c < NCHUNK; c++) {
        const uint32_t stA = base + (uint32_t)(c & 1) * STAGE_BYTES;
        const uint32_t stB = stA + TILE_BYTES;

        if (c + 1 < NCHUNK) {
            const __nv_bfloat16 *As, *Bs;
            chunk_src(c + 1, As, Bs);
            const uint32_t nA = base + (uint32_t)((c + 1) & 1) * STAGE_BYTES;
            prefetch_tiles(nA, nA + TILE_BYTES, As, Bs, tid);
            CP_COMMIT();
            CP_WAIT(1);
        } else {
            CP_WAIT(0);
        }
        __syncthreads();

#pragma unroll
        for (int u = 0; u < 2; u++) {
            uint32_t afr[2][2][4];
#pragma unroll
            for (int mt = 0; mt < 2; mt++)
#pragma unroll
                for (int ks = 0; ks < 2; ks++) {
                    int arow = wm * 32 + mt * 16 + (q & 1) * 8 + r8;
                    int aseg = (2 * u + ks) * 2 + (q >> 1);
                    uint32_t addr = stA + arow * 128 + ((aseg ^ (arow & 7)) << 4);
                    LDSM_X4(afr[mt][ks][0], afr[mt][ks][1],
                            afr[mt][ks][2], afr[mt][ks][3], addr);
                }
#pragma unroll
            for (int nt = 0; nt < 8; nt++) {
                int brow = wn * 64 + nt * 8 + r8;
                int bseg = u * 4 + q;
                uint32_t addr = stB + brow * 128 + ((bseg ^ (brow & 7)) << 4);
                uint32_t t0, t1, t2, t3;
                LDSM_X4(t0, t1, t2, t3, addr);
#pragma unroll
                for (int mt = 0; mt < 2; mt++) {
                    mma16816(acc[mt][nt], afr[mt][0][0], afr[mt][0][1],
                             afr[mt][0][2], afr[mt][0][3], t0, t1);
                    mma16816(acc[mt][nt], afr[mt][1][0], afr[mt][1][1],
                             afr[mt][1][2], afr[mt][1][3], t2, t3);
                }
            }
        }
        __syncthreads();
    }

    // Epilogue
    const int row0 = bm * 128 + wm * 32 + (lane >> 2);
    const int col0 = bn * 128 + wn * 64 + 2 * (lane & 3);
#pragma unroll
    for (int mt = 0; mt < 2; mt++)
#pragma unroll
        for (int nt = 0; nt < 8; nt++) {
            int rr = row0 + mt * 16;
            int cc = col0 + nt * 8;
            float b0 = bias[cc], b1 = bias[cc + 1];
            float v0 = acc[mt][nt][0] + b0, v1 = acc[mt][nt][1] + b1;
            float v2 = acc[mt][nt][2] + b0, v3 = acc[mt][nt][3] + b1;
            if (MODE == 0) {
                *(float2*)&C[(size_t)rr * N + cc]       = make_float2(v0, v1);
                *(float2*)&C[(size_t)(rr + 8) * N + cc] = make_float2(v2, v3);
            } else {
                int tensor = cc / 768;
                int within = cc % 768;
                int hh = within >> 6, dd = within & 63;
                if (tensor == 0) { v0 *= QSCALE; v1 *= QSCALE; v2 *= QSCALE; v3 *= QSCALE; }
                uint32_t h01, l01, h23, l23;
                split_pack(v0, v1, h01, l01);
                split_pack(v2, v3, h23, l23);
                {
                    int bb = rr >> 10, t = rr & 1023;
                    size_t di = (size_t)tensor * TSTRIDE +
                                (size_t)(bb * NH + hh) * (SEQ * HD) + (size_t)t * HD + dd;
                    *(uint32_t*)&outh[di] = h01;
                    *(uint32_t*)&outl[di] = l01;
                }
                {
                    int rr2 = rr + 8;
                    int bb = rr2 >> 10, t = rr2 & 1023;
                    size_t di = (size_t)tensor * TSTRIDE +
                                (size_t)(bb * NH + hh) * (SEQ * HD) + (size_t)t * HD + dd;
                    *(uint32_t*)&outh[di] = h23;
                    *(uint32_t*)&outl[di] = l23;
                }
            }
        }
}

// ---------------------------------------------------------------------------
// Tensor-core causal flash attention (split-3 on QK and PV).
// CTA: 128 threads (4 warps), q-tile 128 rows of one (b,h); warp = 32 rows.
// KV tiles of 64 keys double-buffered via cp.async.
// Scores in log2 units (Q pre-scaled by 0.125*log2e) -> ex2 softmax.
// Output written directly as split bf16 (hi/lo) for the projection GEMM.
// ---------------------------------------------------------------------------
#define FT_BYTES  8192                        // one 64x64 bf16 tile (128B rows)
#define FSTAGE    (4 * FT_BYTES)              // Kh,Kl,Vh,Vl
#define FLASH_SMEM (2 * 16384 + 2 * FSTAGE + 1024)

__device__ __forceinline__ void prefetch_kv(uint32_t dst,
    const __nv_bfloat16* __restrict__ Kh, const __nv_bfloat16* __restrict__ Kl,
    const __nv_bfloat16* __restrict__ Vh, const __nv_bfloat16* __restrict__ Vl,
    int kt, int tid)
{
    const __nv_bfloat16* srcs[4] = {Kh, Kl, Vh, Vl};
#pragma unroll
    for (int t4 = 0; t4 < 4; t4++) {
        const __nv_bfloat16* src = srcs[t4] + (size_t)(kt * 64) * HD;
#pragma unroll
        for (int jj = 0; jj < 4; jj++) {
            int idx = tid + 128 * jj;      // 0..511
            int row = idx >> 3;
            int s   = idx & 7;
            cp16(dst + t4 * FT_BYTES + row * 128 + ((s ^ (row & 7)) << 4),
                 src + (size_t)row * HD + s * 8);
        }
    }
}

__global__ __launch_bounds__(128) void flash_mma(
    const __nv_bfloat16* __restrict__ Sh, const __nv_bfloat16* __restrict__ Sl,
    __nv_bfloat16* __restrict__ ath, __nv_bfloat16* __restrict__ atl)
{
    extern __shared__ char sm_raw[];
    const uint32_t base = (smem_u32(sm_raw) + 1023) & ~1023u;

    const int tid  = threadIdx.x;
    const int lane = tid & 31;
    const int w    = tid >> 5;
    const int qm   = lane >> 3;            // ldsm matrix id
    const int r8   = lane & 7;
    const int tig  = lane & 3;
    const int gid  = lane >> 2;

    const int qt = (SEQ / 128 - 1) - blockIdx.x;   // heavy tiles first
    const int h  = blockIdx.y;
    const int b  = blockIdx.z;
    const int bh = b * NH + h;
    const int qbase = qt * 128;

    const size_t hb = (size_t)bh * (SEQ * HD);
    const __nv_bfloat16* Qhp = Sh + hb;
    const __nv_bfloat16* Qlp = Sl + hb;
    const __nv_bfloat16* Khp = Sh + TSTRIDE + hb;
    const __nv_bfloat16* Klp = Sl + TSTRIDE + hb;
    const __nv_bfloat16* Vhp = Sh + 2 * TSTRIDE + hb;
    const __nv_bfloat16* Vlp = Sl + 2 * TSTRIDE + hb;

    const uint32_t QH_S = base;
    const uint32_t QL_S = base + 16384;
    const uint32_t ST0  = base + 32768;

    // Initial loads: Q (hi+lo) + KV tile 0, one cp.async group
    {
        const __nv_bfloat16* qs[2] = {Qhp, Qlp};
        uint32_t qd[2] = {QH_S, QL_S};
#pragma unroll
        for (int t2 = 0; t2 < 2; t2++)
#pragma unroll
            for (int jj = 0; jj < 8; jj++) {
                int idx = tid + 128 * jj;  // 0..1023
                int row = idx >> 3;
                int s   = idx & 7;
                cp16(qd[t2] + row * 128 + ((s ^ (row & 7)) << 4),
                     qs[t2] + (size_t)(qbase + row) * HD + s * 8);
            }
        prefetch_kv(ST0, Khp, Klp, Vhp, Vlp, 0, tid);
        CP_COMMIT();
    }

    uint32_t qfh[2][4][4], qfl[2][4][4];
    float oacc[2][8][4];
#pragma unroll
    for (int mt = 0; mt < 2; mt++)
#pragma unroll
        for (int nt = 0; nt < 8; nt++)
#pragma unroll
            for (int e = 0; e < 4; e++) oacc[mt][nt][e] = 0.0f;
    float mrow[2][2], lrow[2][2];
#pragma unroll
    for (int mt = 0; mt < 2; mt++)
#pragma unroll
        for (int hf = 0; hf < 2; hf++) { mrow[mt][hf] = -1e30f; lrow[mt][hf] = 0.0f; }

    const int lastkt = 2 * qt + 1;
    const int wrowmax = qbase + w * 32 + 31;

    for (int kt = 0; kt <= lastkt; kt++) {
        const uint32_t SB = ST0 + (uint32_t)(kt & 1) * FSTAGE;

        if (kt < lastkt) {
            prefetch_kv(ST0 + (uint32_t)((kt + 1) & 1) * FSTAGE,
                        Khp, Klp, Vhp, Vlp, kt + 1, tid);
            CP_COMMIT();
            CP_WAIT(1);
        } else {
            CP_WAIT(0);
        }
        __syncthreads();

        if (kt == 0) {
            // Load persistent Q fragments
#pragma unroll
            for (int mt = 0; mt < 2; mt++)
#pragma unroll
                for (int kk = 0; kk < 4; kk++) {
                    int arow = w * 32 + mt * 16 + (qm & 1) * 8 + r8;
                    int aseg = kk * 2 + (qm >> 1);
                    uint32_t sw = ((aseg ^ (arow & 7)) << 4);
                    LDSM_X4(qfh[mt][kk][0], qfh[mt][kk][1], qfh[mt][kk][2], qfh[mt][kk][3],
                            QH_S + arow * 128 + sw);
                    LDSM_X4(qfl[mt][kk][0], qfl[mt][kk][1], qfl[mt][kk][2], qfl[mt][kk][3],
                            QL_S + arow * 128 + sw);
                }
        }

        if (kt * 64 <= wrowmax) {       // warp has at least one unmasked key
            const uint32_t sKh = SB;
            const uint32_t sKl = SB + FT_BYTES;
            const uint32_t sVh = SB + 2 * FT_BYTES;
            const uint32_t sVl = SB + 3 * FT_BYTES;

            // ---- S = Q K^T (3 split terms) ----
            float sacc[2][8][4];
#pragma unroll
            for (int mt = 0; mt < 2; mt++)
#pragma unroll
                for (int nt = 0; nt < 8; nt++)
#pragma unroll
                    for (int e = 0; e < 4; e++) sacc[mt][nt][e] = 0.0f;

#pragma unroll
            for (int u = 0; u < 2; u++)
#pragma unroll
                for (int nt = 0; nt < 8; nt++) {
                    int brow = nt * 8 + r8;
                    int bseg = u * 4 + qm;
                    uint32_t sw = ((bseg ^ (brow & 7)) << 4);
                    uint32_t t0, t1, t2, t3;
                    LDSM_X4(t0, t1, t2, t3, sKh + brow * 128 + sw);
#pragma unroll
                    for (int mt = 0; mt < 2; mt++) {
                        mma16816(sacc[mt][nt], qfh[mt][2 * u][0], qfh[mt][2 * u][1],
                                 qfh[mt][2 * u][2], qfh[mt][2 * u][3], t0, t1);
                        mma16816(sacc[mt][nt], qfh[mt][2 * u + 1][0], qfh[mt][2 * u + 1][1],
                                 qfh[mt][2 * u + 1][2], qfh[mt][2 * u + 1][3], t2, t3);
                        mma16816(sacc[mt][nt], qfl[mt][2 * u][0], qfl[mt][2 * u][1],
                                 qfl[mt][2 * u][2], qfl[mt][2 * u][3], t0, t1);
                        mma16816(sacc[mt][nt], qfl[mt][2 * u + 1][0], qfl[mt][2 * u + 1][1],
                                 qfl[mt][2 * u + 1][2], qfl[mt][2 * u + 1][3], t2, t3);
                    }
                    LDSM_X4(t0, t1, t2, t3, sKl + brow * 128 + sw);
#pragma unroll
                    for (int mt = 0; mt < 2; mt++) {
                        mma16816(sacc[mt][nt], qfh[mt][2 * u][0], qfh[mt][2 * u][1],
                                 qfh[mt][2 * u][2], qfh[mt][2 * u][3], t0, t1);
                        mma16816(sacc[mt][nt], qfh[mt][2 * u + 1][0], qfh[mt][2 * u + 1][1],
                                 qfh[mt][2 * u + 1][2], qfh[mt][2 * u + 1][3], t2, t3);
                    }
                }

            // ---- causal mask ----
            if (kt >= 2 * qt) {
                int qr0 = qbase + w * 32 + gid;
                int kc0 = kt * 64 + 2 * tig;
#pragma unroll
                for (int mt = 0; mt < 2; mt++)
#pragma unroll
                    for (int nt = 0; nt < 8; nt++)
#pragma unroll
                        for (int e = 0; e < 4; e++) {
                            int qr = qr0 + mt * 16 + (e >> 1) * 8;
                            int kc = kc0 + nt * 8 + (e & 1);
                            if (kc > qr) sacc[mt][nt][e] = -1e30f;
                        }
            }

            // ---- online softmax ----
            float corr[2][2], nm[2][2];
#pragma unroll
            for (int mt = 0; mt < 2; mt++)
#pragma unroll
                for (int hf = 0; hf < 2; hf++) {
                    float tm = -1e30f;
#pragma unroll
                    for (int nt = 0; nt < 8; nt++) {
                        tm = fmaxf(tm, sacc[mt][nt][2 * hf]);
                        tm = fmaxf(tm, sacc[mt][nt][2 * hf + 1]);
                    }
                    tm = fmaxf(tm, __shfl_xor_sync(0xffffffffu, tm, 1));
                    tm = fmaxf(tm, __shfl_xor_sync(0xffffffffu, tm, 2));
                    float n = fmaxf(mrow[mt][hf], tm);
                    corr[mt][hf] = ex2f(mrow[mt][hf] - n);
                    nm[mt][hf] = n;
                    mrow[mt][hf] = n;
                }

#pragma unroll
            for (int mt = 0; mt < 2; mt++)
#pragma unroll
                for (int hf = 0; hf < 2; hf++) {
                    float ps = 0.0f;
#pragma unroll
                    for (int nt = 0; nt < 8; nt++) {
                        float p0 = ex2f(sacc[mt][nt][2 * hf]     - nm[mt][hf]);
                        float p1 = ex2f(sacc[mt][nt][2 * hf + 1] - nm[mt][hf]);
                        sacc[mt][nt][2 * hf]     = p0;
                        sacc[mt][nt][2 * hf + 1] = p1;
                        ps += p0 + p1;
                    }
                    lrow[mt][hf] = lrow[mt][hf] * corr[mt][hf] + ps;
                }

#pragma unroll
            for (int mt = 0; mt < 2; mt++)
#pragma unroll
                for (int nt = 0; nt < 8; nt++) {
                    oacc[mt][nt][0] *= corr[mt][0];
                    oacc[mt][nt][1] *= corr[mt][0];
                    oacc[mt][nt][2] *= corr[mt][1];
                    oacc[mt][nt][3] *= corr[mt][1];
                }

            // ---- P split + pack into A-fragments ----
            uint32_t pah[2][4][4], pal[2][4][4];
#pragma unroll
            for (int mt = 0; mt < 2; mt++)
#pragma unroll
                for (int j = 0; j < 4; j++) {
                    split_pack(sacc[mt][2 * j][0],     sacc[mt][2 * j][1],
                               pah[mt][j][0], pal[mt][j][0]);
                    split_pack(sacc[mt][2 * j][2],     sacc[mt][2 * j][3],
                               pah[mt][j][1], pal[mt][j][1]);
                    split_pack(sacc[mt][2 * j + 1][0], sacc[mt][2 * j + 1][1],
                               pah[mt][j][2], pal[mt][j][2]);
                    split_pack(sacc[mt][2 * j + 1][2], sacc[mt][2 * j + 1][3],
                               pah[mt][j][3], pal[mt][j][3]);
                }

            // ---- O += P V (3 split terms), V via ldmatrix.trans ----
#pragma unroll
            for (int j = 0; j < 4; j++)
#pragma unroll
                for (int dp = 0; dp < 4; dp++) {
                    int rowv = j * 16 + (lane & 15);
                    int segv = dp * 2 + (lane >> 4);
                    uint32_t sw = ((segv ^ (rowv & 7)) << 4);
                    uint32_t t0, t1, t2, t3;
                    LDSM_X4T(t0, t1, t2, t3, sVh + rowv * 128 + sw);
#pragma unroll
                    for (int mt = 0; mt < 2; mt++) {
                        mma16816(oacc[mt][2 * dp], pah[mt][j][0], pah[mt][j][1],
                                 pah[mt][j][2], pah[mt][j][3], t0, t1);
                        mma16816(oacc[mt][2 * dp + 1], pah[mt][j][0], pah[mt][j][1],
                                 pah[mt][j][2], pah[mt][j][3], t2, t3);
                        mma16816(oacc[mt][2 * dp], pal[mt][j][0], pal[mt][j][1],
                                 pal[mt][j][2], pal[mt][j][3], t0, t1);
                        mma16816(oacc[mt][2 * dp + 1], pal[mt][j][0], pal[mt][j][1],
                                 pal[mt][j][2], pal[mt][j][3], t2, t3);
                    }
                    LDSM_X4T(t0, t1, t2, t3, sVl + rowv * 128 + sw);
#pragma unroll
                    for (int mt = 0; mt < 2; mt++) {
                        mma16816(oacc[mt][2 * dp], pah[mt][j][0], pah[mt][j][1],
                                 pah[mt][j][2], pah[mt][j][3], t0, t1);
                        mma16816(oacc[mt][2 * dp + 1], pah[mt][j][0], pah[mt][j][1],
                                 pah[mt][j][2], pah[mt][j][3], t2, t3);
                    }
                }
        }
        __syncthreads();
    }

    // ---- epilogue: normalize, split, write att (hi/lo) ----
    float inv[2][2];
#pragma unroll
    for (int mt = 0; mt < 2; mt++)
#pragma unroll
        for (int hf = 0; hf < 2; hf++) {
            float lv = lrow[mt][hf];
            lv += __shfl_xor_sync(0xffffffffu, lv, 1);
            lv += __shfl_xor_sync(0xffffffffu, lv, 2);
            inv[mt][hf] = 1.0f / lv;
        }

#pragma unroll
    for (int mt = 0; mt < 2; mt++)
#pragma unroll
        for (int nt = 0; nt < 8; nt++) {
            int t0r = qbase + w * 32 + mt * 16 + gid;
            int col = h * HD + nt * 8 + 2 * tig;
            {
                float v0 = oacc[mt][nt][0] * inv[mt][0];
                float v1 = oacc[mt][nt][1] * inv[mt][0];
                uint32_t hp, lp;
                split_pack(v0, v1, hp, lp);
                size_t di = (size_t)(b * SEQ + t0r) * EMB + col;
                *(uint32_t*)&ath[di] = hp;
                *(uint32_t*)&atl[di] = lp;
            }
            {
                float v2 = oacc[mt][nt][2] * inv[mt][1];
                float v3 = oacc[mt][nt][3] * inv[mt][1];
                uint32_t hp, lp;
                split_pack(v2, v3, hp, lp);
                size_t di = (size_t)(b * SEQ + t0r + 8) * EMB + col;
                *(uint32_t*)&ath[di] = hp;
                *(uint32_t*)&atl[di] = lp;
            }
        }
}

// ---------------------------------------------------------------------------
extern "C" void kernel_launch(void* const* d_in, const int* in_sizes, int n_in,
                              void* d_out, int out_size)
{
    (void)in_sizes; (void)n_in; (void)out_size;
    const float* x      = (const float*)d_in[0];
    const float* W_attn = (const float*)d_in[1];
    const float* b_attn = (const float*)d_in[2];
    const float* W_proj = (const float*)d_in[3];
    const float* b_proj = (const float*)d_in[4];
    float* out = (float*)d_out;

    __nv_bfloat16 *ah, *al, *wath, *watl, *wpth, *wptl, *sh, *sl;
    cudaGetSymbolAddress((void**)&ah, g_Ah);
    cudaGetSymbolAddress((void**)&al, g_Al);
    cudaGetSymbolAddress((void**)&wath, g_WaTh);
    cudaGetSymbolAddress((void**)&watl, g_WaTl);
    cudaGetSymbolAddress((void**)&wpth, g_WpTh);
    cudaGetSymbolAddress((void**)&wptl, g_WpTl);
    cudaGetSymbolAddress((void**)&sh, g_Sh);
    cudaGetSymbolAddress((void**)&sl, g_Sl);

    cudaFuncSetAttribute(gemm_mma<0>, cudaFuncAttributeMaxDynamicSharedMemorySize, GEMM_SMEM);
    cudaFuncSetAttribute(gemm_mma<1>, cudaFuncAttributeMaxDynamicSharedMemorySize, GEMM_SMEM);
    cudaFuncSetAttribute(flash_mma,  cudaFuncAttributeMaxDynamicSharedMemorySize, FLASH_SMEM);

    // Prologue: split x, transpose+split weights
    {
        int n = MROWS * EMB;
        split2<<<(n + 255) / 256, 256>>>(x, ah, al, n);
    }
    transpose_split<<<dim3(QKVN / 32, EMB / 32), dim3(32, 8)>>>(W_attn, wath, watl, EMB, QKVN);
    transpose_split<<<dim3(EMB / 32, EMB / 32), dim3(32, 8)>>>(W_proj, wpth, wptl, EMB, EMB);

    // 1) QKV GEMM -> split, head-major, q pre-scaled
    gemm_mma<1><<<dim3(QKVN / 128, MROWS / 128), 256, GEMM_SMEM>>>(
        ah, al, wath, watl, b_attn, nullptr, QKVN, sh, sl);

    // 2) tensor-core causal flash attention -> att split (reuses ah/al)
    flash_mma<<<dim3(SEQ / 128, NH, BATCH), 128, FLASH_SMEM>>>(sh, sl, ah, al);

    // 3) projection GEMM -> out fp32
    gemm_mma<0><<<dim3(EMB / 128, MROWS / 128), 256, GEMM_SMEM>>>(
        ah, al, wpth, wptl, b_proj, out, EMB, nullptr, nullptr);
}

// round 9
// speedup vs baseline: 3.4434x; 1.1380x over previous
#include <cuda_runtime.h>
#include <cuda_bf16.h>
#include <cstdint>
#include <math.h>

#define EMB   768
#define NH    12
#define HD    64
#define BATCH 8
#define SEQ   1024
#define MROWS (BATCH * SEQ)      // 8192
#define QKVN  (3 * EMB)          // 2304

// 0.125 (1/sqrt(64)) * log2(e): folded into Q so softmax uses ex2
#define QSCALE 0.18033688011112042f

#define TSTRIDE ((size_t)BATCH * NH * SEQ * HD)   // elems per q/k/v tensor

// ---------------------------------------------------------------------------
// Scratch (no allocations allowed)
// ---------------------------------------------------------------------------
__device__ __align__(256) __nv_bfloat16 g_Ah[(size_t)MROWS * EMB];
__device__ __align__(256) __nv_bfloat16 g_Al[(size_t)MROWS * EMB];
__device__ __align__(256) __nv_bfloat16 g_WaTh[(size_t)QKVN * EMB];
__device__ __align__(256) __nv_bfloat16 g_WaTl[(size_t)QKVN * EMB];
__device__ __align__(256) __nv_bfloat16 g_WpTh[(size_t)EMB * EMB];
__device__ __align__(256) __nv_bfloat16 g_WpTl[(size_t)EMB * EMB];
__device__ __align__(256) __nv_bfloat16 g_Sh[3 * TSTRIDE];
__device__ __align__(256) __nv_bfloat16 g_Sl[3 * TSTRIDE];

// ---------------------------------------------------------------------------
// PTX helpers (sm_80-class only; toolchain targets plain sm_103)
// ---------------------------------------------------------------------------
__device__ __forceinline__ uint32_t smem_u32(const void* p) {
    uint32_t a;
    asm("{ .reg .u64 t; cvta.to.shared.u64 t, %1; cvt.u32.u64 %0, t; }"
        : "=r"(a) : "l"(p));
    return a;
}
__device__ __forceinline__ void cp16(uint32_t dst, const void* src) {
    asm volatile("cp.async.cg.shared.global [%0], [%1], 16;"
                 :: "r"(dst), "l"(src) : "memory");
}
#define CP_COMMIT() asm volatile("cp.async.commit_group;" ::: "memory")
#define CP_WAIT(n)  asm volatile("cp.async.wait_group %0;" :: "n"(n) : "memory")

#define LDSM_X4(r0, r1, r2, r3, addr) \
    asm volatile("ldmatrix.sync.aligned.m8n8.x4.shared.b16 {%0,%1,%2,%3}, [%4];" \
                 : "=r"(r0), "=r"(r1), "=r"(r2), "=r"(r3) : "r"(addr))
#define LDSM_X4T(r0, r1, r2, r3, addr) \
    asm volatile("ldmatrix.sync.aligned.m8n8.x4.trans.shared.b16 {%0,%1,%2,%3}, [%4];" \
                 : "=r"(r0), "=r"(r1), "=r"(r2), "=r"(r3) : "r"(addr))

__device__ __forceinline__ void mma16816(float* d,
                                         uint32_t a0, uint32_t a1, uint32_t a2, uint32_t a3,
                                         uint32_t b0, uint32_t b1) {
    asm volatile("mma.sync.aligned.m16n8k16.row.col.f32.bf16.bf16.f32 "
                 "{%0,%1,%2,%3}, {%4,%5,%6,%7}, {%8,%9}, {%0,%1,%2,%3};"
                 : "+f"(d[0]), "+f"(d[1]), "+f"(d[2]), "+f"(d[3])
                 : "r"(a0), "r"(a1), "r"(a2), "r"(a3), "r"(b0), "r"(b1));
}

__device__ __forceinline__ float ex2f(float x) {
    float y;
    asm("ex2.approx.ftz.f32 %0, %1;" : "=f"(y) : "f"(x));
    return y;
}
__device__ __forceinline__ uint32_t pack_bf2(__nv_bfloat16 lo, __nv_bfloat16 hi) {
    __nv_bfloat162 t = __halves2bfloat162(lo, hi);
    return *reinterpret_cast<uint32_t*>(&t);
}
__device__ __forceinline__ void split_pack(float p0, float p1, uint32_t& hi, uint32_t& lo) {
    __nv_bfloat16 h0 = __float2bfloat16_rn(p0);
    __nv_bfloat16 h1 = __float2bfloat16_rn(p1);
    float r0 = p0 - __bfloat162float(h0);
    float r1 = p1 - __bfloat162float(h1);
    hi = pack_bf2(h0, h1);
    lo = pack_bf2(__float2bfloat16_rn(r0), __float2bfloat16_rn(r1));
}

// ---------------------------------------------------------------------------
// Prologue kernels
// ---------------------------------------------------------------------------
__global__ __launch_bounds__(256) void split2(const float* __restrict__ src,
                                              __nv_bfloat16* __restrict__ hi,
                                              __nv_bfloat16* __restrict__ lo, int n)
{
    int i = blockIdx.x * blockDim.x + threadIdx.x;
    if (i < n) {
        float v = src[i];
        __nv_bfloat16 h = __float2bfloat16(v);
        hi[i] = h;
        lo[i] = __float2bfloat16(v - __bfloat162float(h));
    }
}

__global__ __launch_bounds__(256) void transpose_split(
    const float* __restrict__ W, __nv_bfloat16* __restrict__ Th,
    __nv_bfloat16* __restrict__ Tl, int K, int N)
{
    __shared__ float t[32][33];
    int k0 = blockIdx.y * 32, n0 = blockIdx.x * 32;
#pragma unroll
    for (int r = 0; r < 32; r += 8) {
        int k = k0 + threadIdx.y + r;
        int n = n0 + threadIdx.x;
        t[threadIdx.y + r][threadIdx.x] = W[(size_t)k * N + n];
    }
    __syncthreads();
#pragma unroll
    for (int r = 0; r < 32; r += 8) {
        int n = n0 + threadIdx.y + r;
        int k = k0 + threadIdx.x;
        float v = t[threadIdx.x][threadIdx.y + r];
        __nv_bfloat16 h = __float2bfloat16(v);
        Th[(size_t)n * K + k] = h;
        Tl[(size_t)n * K + k] = __float2bfloat16(v - __bfloat162float(h));
    }
}

// ---------------------------------------------------------------------------
// Fused split-3 mma.sync GEMM: C = A@B^T + bias with A=Ah+Al, B=Bh+Bl,
// C ~= AhBh + AlBh + AhBl (fp32 accum).
// CTA tile 256x128, 8 warps (4 along M x 2 along N), warp tile 64x64.
// 12 chunks of K=64; per chunk the 4 tiles (Ah,Al,Bh,Bl) are loaded ONCE.
// 2-stage cp.async double buffer (96 KB/stage).
// MODE 0: fp32 out + bias.  MODE 1: qkv epilogue (split + head-major scatter).
// ---------------------------------------------------------------------------
#define AH_OFF      0
#define AL_OFF      32768
#define BH_OFF      65536
#define BL_OFF      81920
#define STAGE_BYTES 98304
#define GEMM_SMEM   (2 * STAGE_BYTES + 1024)
#define NCHUNK      12

template <int MODE>
__global__ __launch_bounds__(256) void gemm_mma(
    const __nv_bfloat16* __restrict__ Ah, const __nv_bfloat16* __restrict__ Al,
    const __nv_bfloat16* __restrict__ Bh, const __nv_bfloat16* __restrict__ Bl,
    const float* __restrict__ bias, float* __restrict__ C, int N,
    __nv_bfloat16* __restrict__ outh, __nv_bfloat16* __restrict__ outl)
{
    extern __shared__ char sm_raw[];
    const uint32_t base = (smem_u32(sm_raw) + 1023) & ~1023u;

    const int tid  = threadIdx.x;
    const int lane = tid & 31;
    const int w    = tid >> 5;
    const int wm   = w & 3;               // 0..3 -> 64-row slice
    const int wn   = w >> 2;              // 0..1 -> 64-col slice
    const int bn   = blockIdx.x;
    const int bm   = blockIdx.y;

    const __nv_bfloat16* Abh = Ah + (size_t)bm * 256 * EMB;
    const __nv_bfloat16* Abl = Al + (size_t)bm * 256 * EMB;
    const __nv_bfloat16* Bbh = Bh + (size_t)bn * 128 * EMB;
    const __nv_bfloat16* Bbl = Bl + (size_t)bn * 128 * EMB;

    float acc[4][8][4];
#pragma unroll
    for (int mt = 0; mt < 4; mt++)
#pragma unroll
        for (int nt = 0; nt < 8; nt++)
#pragma unroll
            for (int e = 0; e < 4; e++) acc[mt][nt][e] = 0.0f;

    auto prefetch = [&](int c) {
        const uint32_t stg = base + (uint32_t)(c & 1) * STAGE_BYTES;
        const int koff = c * 64;
#pragma unroll
        for (int j = 0; j < 8; j++) {
            int idx = tid + 256 * j;          // 0..2047
            int row = idx >> 3;               // 0..255
            int s   = idx & 7;
            uint32_t off = (uint32_t)(row * 128 + (((s ^ (row & 7))) << 4));
            size_t g = (size_t)row * EMB + koff + s * 8;
            cp16(stg + AH_OFF + off, Abh + g);
            cp16(stg + AL_OFF + off, Abl + g);
        }
#pragma unroll
        for (int j = 0; j < 4; j++) {
            int idx = tid + 256 * j;          // 0..1023
            int row = idx >> 3;               // 0..127
            int s   = idx & 7;
            uint32_t off = (uint32_t)(row * 128 + (((s ^ (row & 7))) << 4));
            size_t g = (size_t)row * EMB + koff + s * 8;
            cp16(stg + BH_OFF + off, Bbh + g);
            cp16(stg + BL_OFF + off, Bbl + g);
        }
    };

    prefetch(0);
    CP_COMMIT();

    const int q  = lane >> 3;
    const int r8 = lane & 7;

    for (int c = 0; c < NCHUNK; c++) {
        const uint32_t stg = base + (uint32_t)(c & 1) * STAGE_BYTES;

        if (c + 1 < NCHUNK) {
            prefetch(c + 1);
            CP_COMMIT();
            CP_WAIT(1);
        } else {
            CP_WAIT(0);
        }
        __syncthreads();

#pragma unroll
        for (int u = 0; u < 2; u++) {
            uint32_t af[4][2][4];
            // ---- Ah fragments for this k32 half ----
#pragma unroll
            for (int mt = 0; mt < 4; mt++)
#pragma unroll
                for (int ks = 0; ks < 2; ks++) {
                    int arow = wm * 64 + mt * 16 + (q & 1) * 8 + r8;
                    int aseg = (2 * u + ks) * 2 + (q >> 1);
                    uint32_t addr = stg + AH_OFF + arow * 128 + ((aseg ^ (arow & 7)) << 4);
                    LDSM_X4(af[mt][ks][0], af[mt][ks][1], af[mt][ks][2], af[mt][ks][3], addr);
                }
            // ---- pass 1: Ah*Bh and Ah*Bl ----
#pragma unroll
            for (int nt = 0; nt < 8; nt++) {
                int brow = wn * 64 + nt * 8 + r8;
                int bseg = u * 4 + q;
                uint32_t bsw = ((bseg ^ (brow & 7)) << 4);
                uint32_t t0, t1, t2, t3;
                LDSM_X4(t0, t1, t2, t3, stg + BH_OFF + brow * 128 + bsw);
#pragma unroll
                for (int mt = 0; mt < 4; mt++) {
                    mma16816(acc[mt][nt], af[mt][0][0], af[mt][0][1],
                             af[mt][0][2], af[mt][0][3], t0, t1);
                    mma16816(acc[mt][nt], af[mt][1][0], af[mt][1][1],
                             af[mt][1][2], af[mt][1][3], t2, t3);
                }
                LDSM_X4(t0, t1, t2, t3, stg + BL_OFF + brow * 128 + bsw);
#pragma unroll
                for (int mt = 0; mt < 4; mt++) {
                    mma16816(acc[mt][nt], af[mt][0][0], af[mt][0][1],
                             af[mt][0][2], af[mt][0][3], t0, t1);
                    mma16816(acc[mt][nt], af[mt][1][0], af[mt][1][1],
                             af[mt][1][2], af[mt][1][3], t2, t3);
                }
            }
            // ---- Al fragments (overwrite af) ----
#pragma unroll
            for (int mt = 0; mt < 4; mt++)
#pragma unroll
                for (int ks = 0; ks < 2; ks++) {
                    int arow = wm * 64 + mt * 16 + (q & 1) * 8 + r8;
                    int aseg = (2 * u + ks) * 2 + (q >> 1);
                    uint32_t addr = stg + AL_OFF + arow * 128 + ((aseg ^ (arow & 7)) << 4);
                    LDSM_X4(af[mt][ks][0], af[mt][ks][1], af[mt][ks][2], af[mt][ks][3], addr);
                }
            // ---- pass 2: Al*Bh ----
#pragma unroll
            for (int nt = 0; nt < 8; nt++) {
                int brow = wn * 64 + nt * 8 + r8;
                int bseg = u * 4 + q;
                uint32_t t0, t1, t2, t3;
                LDSM_X4(t0, t1, t2, t3,
                        stg + BH_OFF + brow * 128 + ((bseg ^ (brow & 7)) << 4));
#pragma unroll
                for (int mt = 0; mt < 4; mt++) {
                    mma16816(acc[mt][nt], af[mt][0][0], af[mt][0][1],
                             af[mt][0][2], af[mt][0][3], t0, t1);
                    mma16816(acc[mt][nt], af[mt][1][0], af[mt][1][1],
                             af[mt][1][2], af[mt][1][3], t2, t3);
                }
            }
        }
        __syncthreads();
    }

    // ---- epilogue ----
    const int row0 = bm * 256 + wm * 64 + (lane >> 2);
    const int col0 = bn * 128 + wn * 64 + 2 * (lane & 3);
#pragma unroll
    for (int mt = 0; mt < 4; mt++)
#pragma unroll
        for (int nt = 0; nt < 8; nt++) {
            int rr = row0 + mt * 16;
            int cc = col0 + nt * 8;
            float b0 = bias[cc], b1 = bias[cc + 1];
            float v0 = acc[mt][nt][0] + b0, v1 = acc[mt][nt][1] + b1;
            float v2 = acc[mt][nt][2] + b0, v3 = acc[mt][nt][3] + b1;
            if (MODE == 0) {
                *(float2*)&C[(size_t)rr * N + cc]       = make_float2(v0, v1);
                *(float2*)&C[(size_t)(rr + 8) * N + cc] = make_float2(v2, v3);
            } else {
                int tensor = cc / 768;
                int within = cc % 768;
                int hh = within >> 6, dd = within & 63;
                if (tensor == 0) { v0 *= QSCALE; v1 *= QSCALE; v2 *= QSCALE; v3 *= QSCALE; }
                uint32_t h01, l01, h23, l23;
                split_pack(v0, v1, h01, l01);
                split_pack(v2, v3, h23, l23);
                {
                    int bb = rr >> 10, t = rr & 1023;
                    size_t di = (size_t)tensor * TSTRIDE +
                                (size_t)(bb * NH + hh) * (SEQ * HD) + (size_t)t * HD + dd;
                    *(uint32_t*)&outh[di] = h01;
                    *(uint32_t*)&outl[di] = l01;
                }
                {
                    int rr2 = rr + 8;
                    int bb = rr2 >> 10, t = rr2 & 1023;
                    size_t di = (size_t)tensor * TSTRIDE +
                                (size_t)(bb * NH + hh) * (SEQ * HD) + (size_t)t * HD + dd;
                    *(uint32_t*)&outh[di] = h23;
                    *(uint32_t*)&outl[di] = l23;
                }
            }
        }
}

// ---------------------------------------------------------------------------
// Tensor-core causal flash attention (unchanged from R7 — verified)
// ---------------------------------------------------------------------------
#define FT_BYTES  8192
#define FSTAGE    (4 * FT_BYTES)
#define FLASH_SMEM (2 * 16384 + 2 * FSTAGE + 1024)

__device__ __forceinline__ void prefetch_kv(uint32_t dst,
    const __nv_bfloat16* __restrict__ Kh, const __nv_bfloat16* __restrict__ Kl,
    const __nv_bfloat16* __restrict__ Vh, const __nv_bfloat16* __restrict__ Vl,
    int kt, int tid)
{
    const __nv_bfloat16* srcs[4] = {Kh, Kl, Vh, Vl};
#pragma unroll
    for (int t4 = 0; t4 < 4; t4++) {
        const __nv_bfloat16* src = srcs[t4] + (size_t)(kt * 64) * HD;
#pragma unroll
        for (int jj = 0; jj < 4; jj++) {
            int idx = tid + 128 * jj;
            int row = idx >> 3;
            int s   = idx & 7;
            cp16(dst + t4 * FT_BYTES + row * 128 + ((s ^ (row & 7)) << 4),
                 src + (size_t)row * HD + s * 8);
        }
    }
}

__global__ __launch_bounds__(128) void flash_mma(
    const __nv_bfloat16* __restrict__ Sh, const __nv_bfloat16* __restrict__ Sl,
    __nv_bfloat16* __restrict__ ath, __nv_bfloat16* __restrict__ atl)
{
    extern __shared__ char sm_raw[];
    const uint32_t base = (smem_u32(sm_raw) + 1023) & ~1023u;

    const int tid  = threadIdx.x;
    const int lane = tid & 31;
    const int w    = tid >> 5;
    const int qm   = lane >> 3;
    const int r8   = lane & 7;
    const int tig  = lane & 3;
    const int gid  = lane >> 2;

    const int qt = (SEQ / 128 - 1) - blockIdx.x;
    const int h  = blockIdx.y;
    const int b  = blockIdx.z;
    const int bh = b * NH + h;
    const int qbase = qt * 128;

    const size_t hb = (size_t)bh * (SEQ * HD);
    const __nv_bfloat16* Qhp = Sh + hb;
    const __nv_bfloat16* Qlp = Sl + hb;
    const __nv_bfloat16* Khp = Sh + TSTRIDE + hb;
    const __nv_bfloat16* Klp = Sl + TSTRIDE + hb;
    const __nv_bfloat16* Vhp = Sh + 2 * TSTRIDE + hb;
    const __nv_bfloat16* Vlp = Sl + 2 * TSTRIDE + hb;

    const uint32_t QH_S = base;
    const uint32_t QL_S = base + 16384;
    const uint32_t ST0  = base + 32768;

    {
        const __nv_bfloat16* qs[2] = {Qhp, Qlp};
        uint32_t qd[2] = {QH_S, QL_S};
#pragma unroll
        for (int t2 = 0; t2 < 2; t2++)
#pragma unroll
            for (int jj = 0; jj < 8; jj++) {
                int idx = tid + 128 * jj;
                int row = idx >> 3;
                int s   = idx & 7;
                cp16(qd[t2] + row * 128 + ((s ^ (row & 7)) << 4),
                     qs[t2] + (size_t)(qbase + row) * HD + s * 8);
            }
        prefetch_kv(ST0, Khp, Klp, Vhp, Vlp, 0, tid);
        CP_COMMIT();
    }

    uint32_t qfh[2][4][4], qfl[2][4][4];
    float oacc[2][8][4];
#pragma unroll
    for (int mt = 0; mt < 2; mt++)
#pragma unroll
        for (int nt = 0; nt < 8; nt++)
#pragma unroll
            for (int e = 0; e < 4; e++) oacc[mt][nt][e] = 0.0f;
    float mrow[2][2], lrow[2][2];
#pragma unroll
    for (int mt = 0; mt < 2; mt++)
#pragma unroll
        for (int hf = 0; hf < 2; hf++) { mrow[mt][hf] = -1e30f; lrow[mt][hf] = 0.0f; }

    const int lastkt = 2 * qt + 1;
    const int wrowmax = qbase + w * 32 + 31;

    for (int kt = 0; kt <= lastkt; kt++) {
        const uint32_t SB = ST0 + (uint32_t)(kt & 1) * FSTAGE;

        if (kt < lastkt) {
            prefetch_kv(ST0 + (uint32_t)((kt + 1) & 1) * FSTAGE,
                        Khp, Klp, Vhp, Vlp, kt + 1, tid);
            CP_COMMIT();
            CP_WAIT(1);
        } else {
            CP_WAIT(0);
        }
        __syncthreads();

        if (kt == 0) {
#pragma unroll
            for (int mt = 0; mt < 2; mt++)
#pragma unroll
                for (int kk = 0; kk < 4; kk++) {
                    int arow = w * 32 + mt * 16 + (qm & 1) * 8 + r8;
                    int aseg = kk * 2 + (qm >> 1);
                    uint32_t sw = ((aseg ^ (arow & 7)) << 4);
                    LDSM_X4(qfh[mt][kk][0], qfh[mt][kk][1], qfh[mt][kk][2], qfh[mt][kk][3],
                            QH_S + arow * 128 + sw);
                    LDSM_X4(qfl[mt][kk][0], qfl[mt][kk][1], qfl[mt][kk][2], qfl[mt][kk][3],
                            QL_S + arow * 128 + sw);
                }
        }

        if (kt * 64 <= wrowmax) {
            const uint32_t sKh = SB;
            const uint32_t sKl = SB + FT_BYTES;
            const uint32_t sVh = SB + 2 * FT_BYTES;
            const uint32_t sVl = SB + 3 * FT_BYTES;

            float sacc[2][8][4];
#pragma unroll
            for (int mt = 0; mt < 2; mt++)
#pragma unroll
                for (int nt = 0; nt < 8; nt++)
#pragma unroll
                    for (int e = 0; e < 4; e++) sacc[mt][nt][e] = 0.0f;

#pragma unroll
            for (int u = 0; u < 2; u++)
#pragma unroll
                for (int nt = 0; nt < 8; nt++) {
                    int brow = nt * 8 + r8;
                    int bseg = u * 4 + qm;
                    uint32_t sw = ((bseg ^ (brow & 7)) << 4);
                    uint32_t t0, t1, t2, t3;
                    LDSM_X4(t0, t1, t2, t3, sKh + brow * 128 + sw);
#pragma unroll
                    for (int mt = 0; mt < 2; mt++) {
                        mma16816(sacc[mt][nt], qfh[mt][2 * u][0], qfh[mt][2 * u][1],
                                 qfh[mt][2 * u][2], qfh[mt][2 * u][3], t0, t1);
                        mma16816(sacc[mt][nt], qfh[mt][2 * u + 1][0], qfh[mt][2 * u + 1][1],
                                 qfh[mt][2 * u + 1][2], qfh[mt][2 * u + 1][3], t2, t3);
                        mma16816(sacc[mt][nt], qfl[mt][2 * u][0], qfl[mt][2 * u][1],
                                 qfl[mt][2 * u][2], qfl[mt][2 * u][3], t0, t1);
                        mma16816(sacc[mt][nt], qfl[mt][2 * u + 1][0], qfl[mt][2 * u + 1][1],
                                 qfl[mt][2 * u + 1][2], qfl[mt][2 * u + 1][3], t2, t3);
                    }
                    LDSM_X4(t0, t1, t2, t3, sKl + brow * 128 + sw);
#pragma unroll
                    for (int mt = 0; mt < 2; mt++) {
                        mma16816(sacc[mt][nt], qfh[mt][2 * u][0], qfh[mt][2 * u][1],
                                 qfh[mt][2 * u][2], qfh[mt][2 * u][3], t0, t1);
                        mma16816(sacc[mt][nt], qfh[mt][2 * u + 1][0], qfh[mt][2 * u + 1][1],
                                 qfh[mt][2 * u + 1][2], qfh[mt][2 * u + 1][3], t2, t3);
                    }
                }

            if (kt >= 2 * qt) {
                int qr0 = qbase + w * 32 + gid;
                int kc0 = kt * 64 + 2 * tig;
#pragma unroll
                for (int mt = 0; mt < 2; mt++)
#pragma unroll
                    for (int nt = 0; nt < 8; nt++)
#pragma unroll
                        for (int e = 0; e < 4; e++) {
                            int qr = qr0 + mt * 16 + (e >> 1) * 8;
                            int kc = kc0 + nt * 8 + (e & 1);
                            if (kc > qr) sacc[mt][nt][e] = -1e30f;
                        }
            }

            float corr[2][2], nm[2][2];
#pragma unroll
            for (int mt = 0; mt < 2; mt++)
#pragma unroll
                for (int hf = 0; hf < 2; hf++) {
                    float tm = -1e30f;
#pragma unroll
                    for (int nt = 0; nt < 8; nt++) {
                        tm = fmaxf(tm, sacc[mt][nt][2 * hf]);
                        tm = fmaxf(tm, sacc[mt][nt][2 * hf + 1]);
                    }
                    tm = fmaxf(tm, __shfl_xor_sync(0xffffffffu, tm, 1));
                    tm = fmaxf(tm, __shfl_xor_sync(0xffffffffu, tm, 2));
                    float n = fmaxf(mrow[mt][hf], tm);
                    corr[mt][hf] = ex2f(mrow[mt][hf] - n);
                    nm[mt][hf] = n;
                    mrow[mt][hf] = n;
                }

#pragma unroll
            for (int mt = 0; mt < 2; mt++)
#pragma unroll
                for (int hf = 0; hf < 2; hf++) {
                    float ps = 0.0f;
#pragma unroll
                    for (int nt = 0; nt < 8; nt++) {
                        float p0 = ex2f(sacc[mt][nt][2 * hf]     - nm[mt][hf]);
                        float p1 = ex2f(sacc[mt][nt][2 * hf + 1] - nm[mt][hf]);
                        sacc[mt][nt][2 * hf]     = p0;
                        sacc[mt][nt][2 * hf + 1] = p1;
                        ps += p0 + p1;
                    }
                    lrow[mt][hf] = lrow[mt][hf] * corr[mt][hf] + ps;
                }

#pragma unroll
            for (int mt = 0; mt < 2; mt++)
#pragma unroll
                for (int nt = 0; nt < 8; nt++) {
                    oacc[mt][nt][0] *= corr[mt][0];
                    oacc[mt][nt][1] *= corr[mt][0];
                    oacc[mt][nt][2] *= corr[mt][1];
                    oacc[mt][nt][3] *= corr[mt][1];
                }

            uint32_t pah[2][4][4], pal[2][4][4];
#pragma unroll
            for (int mt = 0; mt < 2; mt++)
#pragma unroll
                for (int j = 0; j < 4; j++) {
                    split_pack(sacc[mt][2 * j][0],     sacc[mt][2 * j][1],
                               pah[mt][j][0], pal[mt][j][0]);
                    split_pack(sacc[mt][2 * j][2],     sacc[mt][2 * j][3],
                               pah[mt][j][1], pal[mt][j][1]);
                    split_pack(sacc[mt][2 * j + 1][0], sacc[mt][2 * j + 1][1],
                               pah[mt][j][2], pal[mt][j][2]);
                    split_pack(sacc[mt][2 * j + 1][2], sacc[mt][2 * j + 1][3],
                               pah[mt][j][3], pal[mt][j][3]);
                }

#pragma unroll
            for (int j = 0; j < 4; j++)
#pragma unroll
                for (int dp = 0; dp < 4; dp++) {
                    int rowv = j * 16 + (lane & 15);
                    int segv = dp * 2 + (lane >> 4);
                    uint32_t sw = ((segv ^ (rowv & 7)) << 4);
                    uint32_t t0, t1, t2, t3;
                    LDSM_X4T(t0, t1, t2, t3, sVh + rowv * 128 + sw);
#pragma unroll
                    for (int mt = 0; mt < 2; mt++) {
                        mma16816(oacc[mt][2 * dp], pah[mt][j][0], pah[mt][j][1],
                                 pah[mt][j][2], pah[mt][j][3], t0, t1);
                        mma16816(oacc[mt][2 * dp + 1], pah[mt][j][0], pah[mt][j][1],
                                 pah[mt][j][2], pah[mt][j][3], t2, t3);
                        mma16816(oacc[mt][2 * dp], pal[mt][j][0], pal[mt][j][1],
                                 pal[mt][j][2], pal[mt][j][3], t0, t1);
                        mma16816(oacc[mt][2 * dp + 1], pal[mt][j][0], pal[mt][j][1],
                                 pal[mt][j][2], pal[mt][j][3], t2, t3);
                    }
                    LDSM_X4T(t0, t1, t2, t3, sVl + rowv * 128 + sw);
#pragma unroll
                    for (int mt = 0; mt < 2; mt++) {
                        mma16816(oacc[mt][2 * dp], pah[mt][j][0], pah[mt][j][1],
                                 pah[mt][j][2], pah[mt][j][3], t0, t1);
                        mma16816(oacc[mt][2 * dp + 1], pah[mt][j][0], pah[mt][j][1],
                                 pah[mt][j][2], pah[mt][j][3], t2, t3);
                    }
                }
        }
        __syncthreads();
    }

    float inv[2][2];
#pragma unroll
    for (int mt = 0; mt < 2; mt++)
#pragma unroll
        for (int hf = 0; hf < 2; hf++) {
            float lv = lrow[mt][hf];
            lv += __shfl_xor_sync(0xffffffffu, lv, 1);
            lv += __shfl_xor_sync(0xffffffffu, lv, 2);
            inv[mt][hf] = 1.0f / lv;
        }

#pragma unroll
    for (int mt = 0; mt < 2; mt++)
#pragma unroll
        for (int nt = 0; nt < 8; nt++) {
            int t0r = qbase + w * 32 + mt * 16 + gid;
            int col = h * HD + nt * 8 + 2 * tig;
            {
                float v0 = oacc[mt][nt][0] * inv[mt][0];
                float v1 = oacc[mt][nt][1] * inv[mt][0];
                uint32_t hp, lp;
                split_pack(v0, v1, hp, lp);
                size_t di = (size_t)(b * SEQ + t0r) * EMB + col;
                *(uint32_t*)&ath[di] = hp;
                *(uint32_t*)&atl[di] = lp;
            }
            {
                float v2 = oacc[mt][nt][2] * inv[mt][1];
                float v3 = oacc[mt][nt][3] * inv[mt][1];
                uint32_t hp, lp;
                split_pack(v2, v3, hp, lp);
                size_t di = (size_t)(b * SEQ + t0r + 8) * EMB + col;
                *(uint32_t*)&ath[di] = hp;
                *(uint32_t*)&atl[di] = lp;
            }
        }
}

// ---------------------------------------------------------------------------
extern "C" void kernel_launch(void* const* d_in, const int* in_sizes, int n_in,
                              void* d_out, int out_size)
{
    (void)in_sizes; (void)n_in; (void)out_size;
    const float* x      = (const float*)d_in[0];
    const float* W_attn = (const float*)d_in[1];
    const float* b_attn = (const float*)d_in[2];
    const float* W_proj = (const float*)d_in[3];
    const float* b_proj = (const float*)d_in[4];
    float* out = (float*)d_out;

    __nv_bfloat16 *ah, *al, *wath, *watl, *wpth, *wptl, *sh, *sl;
    cudaGetSymbolAddress((void**)&ah, g_Ah);
    cudaGetSymbolAddress((void**)&al, g_Al);
    cudaGetSymbolAddress((void**)&wath, g_WaTh);
    cudaGetSymbolAddress((void**)&watl, g_WaTl);
    cudaGetSymbolAddress((void**)&wpth, g_WpTh);
    cudaGetSymbolAddress((void**)&wptl, g_WpTl);
    cudaGetSymbolAddress((void**)&sh, g_Sh);
    cudaGetSymbolAddress((void**)&sl, g_Sl);

    cudaFuncSetAttribute(gemm_mma<0>, cudaFuncAttributeMaxDynamicSharedMemorySize, GEMM_SMEM);
    cudaFuncSetAttribute(gemm_mma<1>, cudaFuncAttributeMaxDynamicSharedMemorySize, GEMM_SMEM);
    cudaFuncSetAttribute(flash_mma,  cudaFuncAttributeMaxDynamicSharedMemorySize, FLASH_SMEM);

    {
        int n = MROWS * EMB;
        split2<<<(n + 255) / 256, 256>>>(x, ah, al, n);
    }
    transpose_split<<<dim3(QKVN / 32, EMB / 32), dim3(32, 8)>>>(W_attn, wath, watl, EMB, QKVN);
    transpose_split<<<dim3(EMB / 32, EMB / 32), dim3(32, 8)>>>(W_proj, wpth, wptl, EMB, EMB);

    // 1) QKV GEMM -> split bf16, head-major, q pre-scaled
    gemm_mma<1><<<dim3(QKVN / 128, MROWS / 256), 256, GEMM_SMEM>>>(
        ah, al, wath, watl, b_attn, nullptr, QKVN, sh, sl);

    // 2) tensor-core causal flash attention -> att split (reuses ah/al)
    flash_mma<<<dim3(SEQ / 128, NH, BATCH), 128, FLASH_SMEM>>>(sh, sl, ah, al);

    // 3) projection GEMM -> out fp32
    gemm_mma<0><<<dim3(EMB / 128, MROWS / 256), 256, GEMM_SMEM>>>(
        ah, al, wpth, wptl, b_proj, out, EMB, nullptr, nullptr);
}

// round 10
// speedup vs baseline: 3.7902x; 1.1007x over previous
#include <cuda_runtime.h>
#include <cuda_bf16.h>
#include <cstdint>
#include <math.h>

#define EMB   768
#define NH    12
#define HD    64
#define BATCH 8
#define SEQ   1024
#define MROWS (BATCH * SEQ)      // 8192
#define QKVN  (3 * EMB)          // 2304

// 0.125 (1/sqrt(64)) * log2(e): folded into Q so softmax uses ex2
#define QSCALE 0.18033688011112042f

#define TSTRIDE ((size_t)BATCH * NH * SEQ * HD)   // elems per q/k/v tensor

// ---------------------------------------------------------------------------
// Scratch (no allocations allowed)
// ---------------------------------------------------------------------------
__device__ __align__(256) __nv_bfloat16 g_Ah[(size_t)MROWS * EMB];
__device__ __align__(256) __nv_bfloat16 g_Al[(size_t)MROWS * EMB];
__device__ __align__(256) __nv_bfloat16 g_WaTh[(size_t)QKVN * EMB];
__device__ __align__(256) __nv_bfloat16 g_WaTl[(size_t)QKVN * EMB];
__device__ __align__(256) __nv_bfloat16 g_WpTh[(size_t)EMB * EMB];
__device__ __align__(256) __nv_bfloat16 g_WpTl[(size_t)EMB * EMB];
__device__ __align__(256) __nv_bfloat16 g_Sh[3 * TSTRIDE];
__device__ __align__(256) __nv_bfloat16 g_Sl[3 * TSTRIDE];

// ---------------------------------------------------------------------------
// PTX helpers (sm_80-class only; toolchain targets plain sm_103)
// ---------------------------------------------------------------------------
__device__ __forceinline__ uint32_t smem_u32(const void* p) {
    uint32_t a;
    asm("{ .reg .u64 t; cvta.to.shared.u64 t, %1; cvt.u32.u64 %0, t; }"
        : "=r"(a) : "l"(p));
    return a;
}
__device__ __forceinline__ void cp16(uint32_t dst, const void* src) {
    asm volatile("cp.async.cg.shared.global [%0], [%1], 16;"
                 :: "r"(dst), "l"(src) : "memory");
}
#define CP_COMMIT() asm volatile("cp.async.commit_group;" ::: "memory")
#define CP_WAIT(n)  asm volatile("cp.async.wait_group %0;" :: "n"(n) : "memory")

#define LDSM_X4(r0, r1, r2, r3, addr) \
    asm volatile("ldmatrix.sync.aligned.m8n8.x4.shared.b16 {%0,%1,%2,%3}, [%4];" \
                 : "=r"(r0), "=r"(r1), "=r"(r2), "=r"(r3) : "r"(addr))
#define LDSM_X4T(r0, r1, r2, r3, addr) \
    asm volatile("ldmatrix.sync.aligned.m8n8.x4.trans.shared.b16 {%0,%1,%2,%3}, [%4];" \
                 : "=r"(r0), "=r"(r1), "=r"(r2), "=r"(r3) : "r"(addr))

__device__ __forceinline__ void mma16816(float* d,
                                         uint32_t a0, uint32_t a1, uint32_t a2, uint32_t a3,
                                         uint32_t b0, uint32_t b1) {
    asm volatile("mma.sync.aligned.m16n8k16.row.col.f32.bf16.bf16.f32 "
                 "{%0,%1,%2,%3}, {%4,%5,%6,%7}, {%8,%9}, {%0,%1,%2,%3};"
                 : "+f"(d[0]), "+f"(d[1]), "+f"(d[2]), "+f"(d[3])
                 : "r"(a0), "r"(a1), "r"(a2), "r"(a3), "r"(b0), "r"(b1));
}

__device__ __forceinline__ float ex2f(float x) {
    float y;
    asm("ex2.approx.ftz.f32 %0, %1;" : "=f"(y) : "f"(x));
    return y;
}
__device__ __forceinline__ uint32_t pack_bf2(__nv_bfloat16 lo, __nv_bfloat16 hi) {
    __nv_bfloat162 t = __halves2bfloat162(lo, hi);
    return *reinterpret_cast<uint32_t*>(&t);
}
__device__ __forceinline__ void split_pack(float p0, float p1, uint32_t& hi, uint32_t& lo) {
    __nv_bfloat16 h0 = __float2bfloat16_rn(p0);
    __nv_bfloat16 h1 = __float2bfloat16_rn(p1);
    float r0 = p0 - __bfloat162float(h0);
    float r1 = p1 - __bfloat162float(h1);
    hi = pack_bf2(h0, h1);
    lo = pack_bf2(__float2bfloat16_rn(r0), __float2bfloat16_rn(r1));
}

// ---------------------------------------------------------------------------
// Prologue kernels
// ---------------------------------------------------------------------------
__global__ __launch_bounds__(256) void split2(const float* __restrict__ src,
                                              __nv_bfloat16* __restrict__ hi,
                                              __nv_bfloat16* __restrict__ lo, int n)
{
    int i = blockIdx.x * blockDim.x + threadIdx.x;
    if (i < n) {
        float v = src[i];
        __nv_bfloat16 h = __float2bfloat16(v);
        hi[i] = h;
        lo[i] = __float2bfloat16(v - __bfloat162float(h));
    }
}

__global__ __launch_bounds__(256) void transpose_split(
    const float* __restrict__ W, __nv_bfloat16* __restrict__ Th,
    __nv_bfloat16* __restrict__ Tl, int K, int N)
{
    __shared__ float t[32][33];
    int k0 = blockIdx.y * 32, n0 = blockIdx.x * 32;
#pragma unroll
    for (int r = 0; r < 32; r += 8) {
        int k = k0 + threadIdx.y + r;
        int n = n0 + threadIdx.x;
        t[threadIdx.y + r][threadIdx.x] = W[(size_t)k * N + n];
    }
    __syncthreads();
#pragma unroll
    for (int r = 0; r < 32; r += 8) {
        int n = n0 + threadIdx.y + r;
        int k = k0 + threadIdx.x;
        float v = t[threadIdx.x][threadIdx.y + r];
        __nv_bfloat16 h = __float2bfloat16(v);
        Th[(size_t)n * K + k] = h;
        Tl[(size_t)n * K + k] = __float2bfloat16(v - __bfloat162float(h));
    }
}

// ---------------------------------------------------------------------------
// Fused split-3 mma.sync GEMM: C ~= AhBh + AlBh + AhBl (+bias), fp32 accum.
// CTA tile 128x96, 4 warps (2M x 2N), warp tile 64x48.
// 12 chunks of K=64; per chunk each tile loaded ONCE; every Bh/Bl fragment
// loaded once and consumed against both Ah and Al fragments held in regs.
// 2-stage cp.async double buffer (56 KB/stage, 112 KB/CTA -> 2 CTAs/SM).
// MODE 0: fp32 out + bias.  MODE 1: qkv epilogue (split + head-major scatter).
// ---------------------------------------------------------------------------
#define AH_OFF      0
#define AL_OFF      16384
#define BH_OFF      32768
#define BL_OFF      45056
#define STAGE_BYTES 57344
#define GEMM_SMEM   (2 * STAGE_BYTES + 256)
#define NCHUNK      12

template <int MODE>
__global__ __launch_bounds__(128, 2) void gemm_mma(
    const __nv_bfloat16* __restrict__ Ah, const __nv_bfloat16* __restrict__ Al,
    const __nv_bfloat16* __restrict__ Bh, const __nv_bfloat16* __restrict__ Bl,
    const float* __restrict__ bias, float* __restrict__ C, int N,
    __nv_bfloat16* __restrict__ outh, __nv_bfloat16* __restrict__ outl)
{
    extern __shared__ char sm_raw[];
    const uint32_t base = (smem_u32(sm_raw) + 127) & ~127u;

    const int tid  = threadIdx.x;
    const int lane = tid & 31;
    const int w    = tid >> 5;            // 0..3
    const int wm   = w & 1;               // 0..1 -> 64-row slice
    const int wn   = w >> 1;              // 0..1 -> 48-col slice
    const int bn   = blockIdx.x;
    const int bm   = blockIdx.y;

    const __nv_bfloat16* Abh = Ah + (size_t)bm * 128 * EMB;
    const __nv_bfloat16* Abl = Al + (size_t)bm * 128 * EMB;
    const __nv_bfloat16* Bbh = Bh + (size_t)bn * 96 * EMB;
    const __nv_bfloat16* Bbl = Bl + (size_t)bn * 96 * EMB;

    float acc[4][6][4];
#pragma unroll
    for (int mt = 0; mt < 4; mt++)
#pragma unroll
        for (int nt = 0; nt < 6; nt++)
#pragma unroll
            for (int e = 0; e < 4; e++) acc[mt][nt][e] = 0.0f;

    auto prefetch = [&](int c) {
        const uint32_t stg = base + (uint32_t)(c & 1) * STAGE_BYTES;
        const int koff = c * 64;
        // A tiles: 128 rows x 8 segs, hi + lo
#pragma unroll
        for (int j = 0; j < 8; j++) {
            int idx = tid + 128 * j;          // 0..1023
            int row = idx >> 3;               // 0..127
            int s   = idx & 7;
            uint32_t off = (uint32_t)(row * 128 + ((s ^ (row & 7)) << 4));
            size_t g = (size_t)row * EMB + koff + s * 8;
            cp16(stg + AH_OFF + off, Abh + g);
            cp16(stg + AL_OFF + off, Abl + g);
        }
        // B tiles: 96 rows x 8 segs, hi + lo
#pragma unroll
        for (int j = 0; j < 6; j++) {
            int idx = tid + 128 * j;          // 0..767
            int row = idx >> 3;               // 0..95
            int s   = idx & 7;
            uint32_t off = (uint32_t)(row * 128 + ((s ^ (row & 7)) << 4));
            size_t g = (size_t)row * EMB + koff + s * 8;
            cp16(stg + BH_OFF + off, Bbh + g);
            cp16(stg + BL_OFF + off, Bbl + g);
        }
    };

    prefetch(0);
    CP_COMMIT();

    const int qm = lane >> 3;
    const int r8 = lane & 7;

    for (int c = 0; c < NCHUNK; c++) {
        const uint32_t stg = base + (uint32_t)(c & 1) * STAGE_BYTES;

        if (c + 1 < NCHUNK) {
            prefetch(c + 1);
            CP_COMMIT();
            CP_WAIT(1);
        } else {
            CP_WAIT(0);
        }
        __syncthreads();

#pragma unroll
        for (int u = 0; u < 2; u++) {
            // A fragments for this k32 half: hi AND lo live together
            uint32_t ah[4][2][4], al[4][2][4];
#pragma unroll
            for (int mt = 0; mt < 4; mt++)
#pragma unroll
                for (int ks = 0; ks < 2; ks++) {
                    int arow = wm * 64 + mt * 16 + (qm & 1) * 8 + r8;
                    int aseg = (2 * u + ks) * 2 + (qm >> 1);
                    uint32_t sw = arow * 128 + ((aseg ^ (arow & 7)) << 4);
                    LDSM_X4(ah[mt][ks][0], ah[mt][ks][1], ah[mt][ks][2], ah[mt][ks][3],
                            stg + AH_OFF + sw);
                    LDSM_X4(al[mt][ks][0], al[mt][ks][1], al[mt][ks][2], al[mt][ks][3],
                            stg + AL_OFF + sw);
                }
            // each B fragment loaded once, consumed by all products
#pragma unroll
            for (int nt = 0; nt < 6; nt++) {
                int brow = wn * 48 + nt * 8 + r8;
                int bseg = u * 4 + qm;
                uint32_t bsw = brow * 128 + ((bseg ^ (brow & 7)) << 4);
                uint32_t t0, t1, t2, t3;
                LDSM_X4(t0, t1, t2, t3, stg + BH_OFF + bsw);
#pragma unroll
                for (int mt = 0; mt < 4; mt++) {
                    mma16816(acc[mt][nt], ah[mt][0][0], ah[mt][0][1],
                             ah[mt][0][2], ah[mt][0][3], t0, t1);
                    mma16816(acc[mt][nt], ah[mt][1][0], ah[mt][1][1],
                             ah[mt][1][2], ah[mt][1][3], t2, t3);
                    mma16816(acc[mt][nt], al[mt][0][0], al[mt][0][1],
                             al[mt][0][2], al[mt][0][3], t0, t1);
                    mma16816(acc[mt][nt], al[mt][1][0], al[mt][1][1],
                             al[mt][1][2], al[mt][1][3], t2, t3);
                }
                LDSM_X4(t0, t1, t2, t3, stg + BL_OFF + bsw);
#pragma unroll
                for (int mt = 0; mt < 4; mt++) {
                    mma16816(acc[mt][nt], ah[mt][0][0], ah[mt][0][1],
                             ah[mt][0][2], ah[mt][0][3], t0, t1);
                    mma16816(acc[mt][nt], ah[mt][1][0], ah[mt][1][1],
                             ah[mt][1][2], ah[mt][1][3], t2, t3);
                }
            }
        }
        __syncthreads();
    }

    // ---- epilogue ----
    const int row0 = bm * 128 + wm * 64 + (lane >> 2);
    const int col0 = bn * 96 + wn * 48 + 2 * (lane & 3);
#pragma unroll
    for (int mt = 0; mt < 4; mt++)
#pragma unroll
        for (int nt = 0; nt < 6; nt++) {
            int rr = row0 + mt * 16;
            int cc = col0 + nt * 8;
            float b0 = bias[cc], b1 = bias[cc + 1];
            float v0 = acc[mt][nt][0] + b0, v1 = acc[mt][nt][1] + b1;
            float v2 = acc[mt][nt][2] + b0, v3 = acc[mt][nt][3] + b1;
            if (MODE == 0) {
                *(float2*)&C[(size_t)rr * N + cc]       = make_float2(v0, v1);
                *(float2*)&C[(size_t)(rr + 8) * N + cc] = make_float2(v2, v3);
            } else {
                int tensor = cc / 768;
                int within = cc % 768;
                int hh = within >> 6, dd = within & 63;
                if (tensor == 0) { v0 *= QSCALE; v1 *= QSCALE; v2 *= QSCALE; v3 *= QSCALE; }
                uint32_t h01, l01, h23, l23;
                split_pack(v0, v1, h01, l01);
                split_pack(v2, v3, h23, l23);
                {
                    int bb = rr >> 10, t = rr & 1023;
                    size_t di = (size_t)tensor * TSTRIDE +
                                (size_t)(bb * NH + hh) * (SEQ * HD) + (size_t)t * HD + dd;
                    *(uint32_t*)&outh[di] = h01;
                    *(uint32_t*)&outl[di] = l01;
                }
                {
                    int rr2 = rr + 8;
                    int bb = rr2 >> 10, t = rr2 & 1023;
                    size_t di = (size_t)tensor * TSTRIDE +
                                (size_t)(bb * NH + hh) * (SEQ * HD) + (size_t)t * HD + dd;
                    *(uint32_t*)&outh[di] = h23;
                    *(uint32_t*)&outl[di] = l23;
                }
            }
        }
}

// ---------------------------------------------------------------------------
// Tensor-core causal flash attention (unchanged — verified)
// ---------------------------------------------------------------------------
#define FT_BYTES  8192
#define FSTAGE    (4 * FT_BYTES)
#define FLASH_SMEM (2 * 16384 + 2 * FSTAGE + 1024)

__device__ __forceinline__ void prefetch_kv(uint32_t dst,
    const __nv_bfloat16* __restrict__ Kh, const __nv_bfloat16* __restrict__ Kl,
    const __nv_bfloat16* __restrict__ Vh, const __nv_bfloat16* __restrict__ Vl,
    int kt, int tid)
{
    const __nv_bfloat16* srcs[4] = {Kh, Kl, Vh, Vl};
#pragma unroll
    for (int t4 = 0; t4 < 4; t4++) {
        const __nv_bfloat16* src = srcs[t4] + (size_t)(kt * 64) * HD;
#pragma unroll
        for (int jj = 0; jj < 4; jj++) {
            int idx = tid + 128 * jj;
            int row = idx >> 3;
            int s   = idx & 7;
            cp16(dst + t4 * FT_BYTES + row * 128 + ((s ^ (row & 7)) << 4),
                 src + (size_t)row * HD + s * 8);
        }
    }
}

__global__ __launch_bounds__(128) void flash_mma(
    const __nv_bfloat16* __restrict__ Sh, const __nv_bfloat16* __restrict__ Sl,
    __nv_bfloat16* __restrict__ ath, __nv_bfloat16* __restrict__ atl)
{
    extern __shared__ char sm_raw[];
    const uint32_t base = (smem_u32(sm_raw) + 1023) & ~1023u;

    const int tid  = threadIdx.x;
    const int lane = tid & 31;
    const int w    = tid >> 5;
    const int qm   = lane >> 3;
    const int r8   = lane & 7;
    const int tig  = lane & 3;
    const int gid  = lane >> 2;

    const int qt = (SEQ / 128 - 1) - blockIdx.x;
    const int h  = blockIdx.y;
    const int b  = blockIdx.z;
    const int bh = b * NH + h;
    const int qbase = qt * 128;

    const size_t hb = (size_t)bh * (SEQ * HD);
    const __nv_bfloat16* Qhp = Sh + hb;
    const __nv_bfloat16* Qlp = Sl + hb;
    const __nv_bfloat16* Khp = Sh + TSTRIDE + hb;
    const __nv_bfloat16* Klp = Sl + TSTRIDE + hb;
    const __nv_bfloat16* Vhp = Sh + 2 * TSTRIDE + hb;
    const __nv_bfloat16* Vlp = Sl + 2 * TSTRIDE + hb;

    const uint32_t QH_S = base;
    const uint32_t QL_S = base + 16384;
    const uint32_t ST0  = base + 32768;

    {
        const __nv_bfloat16* qs[2] = {Qhp, Qlp};
        uint32_t qd[2] = {QH_S, QL_S};
#pragma unroll
        for (int t2 = 0; t2 < 2; t2++)
#pragma unroll
            for (int jj = 0; jj < 8; jj++) {
                int idx = tid + 128 * jj;
                int row = idx >> 3;
                int s   = idx & 7;
                cp16(qd[t2] + row * 128 + ((s ^ (row & 7)) << 4),
                     qs[t2] + (size_t)(qbase + row) * HD + s * 8);
            }
        prefetch_kv(ST0, Khp, Klp, Vhp, Vlp, 0, tid);
        CP_COMMIT();
    }

    uint32_t qfh[2][4][4], qfl[2][4][4];
    float oacc[2][8][4];
#pragma unroll
    for (int mt = 0; mt < 2; mt++)
#pragma unroll
        for (int nt = 0; nt < 8; nt++)
#pragma unroll
            for (int e = 0; e < 4; e++) oacc[mt][nt][e] = 0.0f;
    float mrow[2][2], lrow[2][2];
#pragma unroll
    for (int mt = 0; mt < 2; mt++)
#pragma unroll
        for (int hf = 0; hf < 2; hf++) { mrow[mt][hf] = -1e30f; lrow[mt][hf] = 0.0f; }

    const int lastkt = 2 * qt + 1;
    const int wrowmax = qbase + w * 32 + 31;

    for (int kt = 0; kt <= lastkt; kt++) {
        const uint32_t SB = ST0 + (uint32_t)(kt & 1) * FSTAGE;

        if (kt < lastkt) {
            prefetch_kv(ST0 + (uint32_t)((kt + 1) & 1) * FSTAGE,
                        Khp, Klp, Vhp, Vlp, kt + 1, tid);
            CP_COMMIT();
            CP_WAIT(1);
        } else {
            CP_WAIT(0);
        }
        __syncthreads();

        if (kt == 0) {
#pragma unroll
            for (int mt = 0; mt < 2; mt++)
#pragma unroll
                for (int kk = 0; kk < 4; kk++) {
                    int arow = w * 32 + mt * 16 + (qm & 1) * 8 + r8;
                    int aseg = kk * 2 + (qm >> 1);
                    uint32_t sw = ((aseg ^ (arow & 7)) << 4);
                    LDSM_X4(qfh[mt][kk][0], qfh[mt][kk][1], qfh[mt][kk][2], qfh[mt][kk][3],
                            QH_S + arow * 128 + sw);
                    LDSM_X4(qfl[mt][kk][0], qfl[mt][kk][1], qfl[mt][kk][2], qfl[mt][kk][3],
                            QL_S + arow * 128 + sw);
                }
        }

        if (kt * 64 <= wrowmax) {
            const uint32_t sKh = SB;
            const uint32_t sKl = SB + FT_BYTES;
            const uint32_t sVh = SB + 2 * FT_BYTES;
            const uint32_t sVl = SB + 3 * FT_BYTES;

            float sacc[2][8][4];
#pragma unroll
            for (int mt = 0; mt < 2; mt++)
#pragma unroll
                for (int nt = 0; nt < 8; nt++)
#pragma unroll
                    for (int e = 0; e < 4; e++) sacc[mt][nt][e] = 0.0f;

#pragma unroll
            for (int u = 0; u < 2; u++)
#pragma unroll
                for (int nt = 0; nt < 8; nt++) {
                    int brow = nt * 8 + r8;
                    int bseg = u * 4 + qm;
                    uint32_t sw = ((bseg ^ (brow & 7)) << 4);
                    uint32_t t0, t1, t2, t3;
                    LDSM_X4(t0, t1, t2, t3, sKh + brow * 128 + sw);
#pragma unroll
                    for (int mt = 0; mt < 2; mt++) {
                        mma16816(sacc[mt][nt], qfh[mt][2 * u][0], qfh[mt][2 * u][1],
                                 qfh[mt][2 * u][2], qfh[mt][2 * u][3], t0, t1);
                        mma16816(sacc[mt][nt], qfh[mt][2 * u + 1][0], qfh[mt][2 * u + 1][1],
                                 qfh[mt][2 * u + 1][2], qfh[mt][2 * u + 1][3], t2, t3);
                        mma16816(sacc[mt][nt], qfl[mt][2 * u][0], qfl[mt][2 * u][1],
                                 qfl[mt][2 * u][2], qfl[mt][2 * u][3], t0, t1);
                        mma16816(sacc[mt][nt], qfl[mt][2 * u + 1][0], qfl[mt][2 * u + 1][1],
                                 qfl[mt][2 * u + 1][2], qfl[mt][2 * u + 1][3], t2, t3);
                    }
                    LDSM_X4(t0, t1, t2, t3, sKl + brow * 128 + sw);
#pragma unroll
                    for (int mt = 0; mt < 2; mt++) {
                        mma16816(sacc[mt][nt], qfh[mt][2 * u][0], qfh[mt][2 * u][1],
                                 qfh[mt][2 * u][2], qfh[mt][2 * u][3], t0, t1);
                        mma16816(sacc[mt][nt], qfh[mt][2 * u + 1][0], qfh[mt][2 * u + 1][1],
                                 qfh[mt][2 * u + 1][2], qfh[mt][2 * u + 1][3], t2, t3);
                    }
                }

            if (kt >= 2 * qt) {
                int qr0 = qbase + w * 32 + gid;
                int kc0 = kt * 64 + 2 * tig;
#pragma unroll
                for (int mt = 0; mt < 2; mt++)
#pragma unroll
                    for (int nt = 0; nt < 8; nt++)
#pragma unroll
                        for (int e = 0; e < 4; e++) {
                            int qr = qr0 + mt * 16 + (e >> 1) * 8;
                            int kc = kc0 + nt * 8 + (e & 1);
                            if (kc > qr) sacc[mt][nt][e] = -1e30f;
                        }
            }

            float corr[2][2], nm[2][2];
#pragma unroll
            for (int mt = 0; mt < 2; mt++)
#pragma unroll
                for (int hf = 0; hf < 2; hf++) {
                    float tm = -1e30f;
#pragma unroll
                    for (int nt = 0; nt < 8; nt++) {
                        tm = fmaxf(tm, sacc[mt][nt][2 * hf]);
                        tm = fmaxf(tm, sacc[mt][nt][2 * hf + 1]);
                    }
                    tm = fmaxf(tm, __shfl_xor_sync(0xffffffffu, tm, 1));
                    tm = fmaxf(tm, __shfl_xor_sync(0xffffffffu, tm, 2));
                    float n = fmaxf(mrow[mt][hf], tm);
                    corr[mt][hf] = ex2f(mrow[mt][hf] - n);
                    nm[mt][hf] = n;
                    mrow[mt][hf] = n;
                }

#pragma unroll
            for (int mt = 0; mt < 2; mt++)
#pragma unroll
                for (int hf = 0; hf < 2; hf++) {
                    float ps = 0.0f;
#pragma unroll
                    for (int nt = 0; nt < 8; nt++) {
                        float p0 = ex2f(sacc[mt][nt][2 * hf]     - nm[mt][hf]);
                        float p1 = ex2f(sacc[mt][nt][2 * hf + 1] - nm[mt][hf]);
                        sacc[mt][nt][2 * hf]     = p0;
                        sacc[mt][nt][2 * hf + 1] = p1;
                        ps += p0 + p1;
                    }
                    lrow[mt][hf] = lrow[mt][hf] * corr[mt][hf] + ps;
                }

#pragma unroll
            for (int mt = 0; mt < 2; mt++)
#pragma unroll
                for (int nt = 0; nt < 8; nt++) {
                    oacc[mt][nt][0] *= corr[mt][0];
                    oacc[mt][nt][1] *= corr[mt][0];
                    oacc[mt][nt][2] *= corr[mt][1];
                    oacc[mt][nt][3] *= corr[mt][1];
                }

            uint32_t pah[2][4][4], pal[2][4][4];
#pragma unroll
            for (int mt = 0; mt < 2; mt++)
#pragma unroll
                for (int j = 0; j < 4; j++) {
                    split_pack(sacc[mt][2 * j][0],     sacc[mt][2 * j][1],
                               pah[mt][j][0], pal[mt][j][0]);
                    split_pack(sacc[mt][2 * j][2],     sacc[mt][2 * j][3],
                               pah[mt][j][1], pal[mt][j][1]);
                    split_pack(sacc[mt][2 * j + 1][0], sacc[mt][2 * j + 1][1],
                               pah[mt][j][2], pal[mt][j][2]);
                    split_pack(sacc[mt][2 * j + 1][2], sacc[mt][2 * j + 1][3],
                               pah[mt][j][3], pal[mt][j][3]);
                }

#pragma unroll
            for (int j = 0; j < 4; j++)
#pragma unroll
                for (int dp = 0; dp < 4; dp++) {
                    int rowv = j * 16 + (lane & 15);
                    int segv = dp * 2 + (lane >> 4);
                    uint32_t sw = ((segv ^ (rowv & 7)) << 4);
                    uint32_t t0, t1, t2, t3;
                    LDSM_X4T(t0, t1, t2, t3, sVh + rowv * 128 + sw);
#pragma unroll
                    for (int mt = 0; mt < 2; mt++) {
                        mma16816(oacc[mt][2 * dp], pah[mt][j][0], pah[mt][j][1],
                                 pah[mt][j][2], pah[mt][j][3], t0, t1);
                        mma16816(oacc[mt][2 * dp + 1], pah[mt][j][0], pah[mt][j][1],
                                 pah[mt][j][2], pah[mt][j][3], t2, t3);
                        mma16816(oacc[mt][2 * dp], pal[mt][j][0], pal[mt][j][1],
                                 pal[mt][j][2], pal[mt][j][3], t0, t1);
                        mma16816(oacc[mt][2 * dp + 1], pal[mt][j][0], pal[mt][j][1],
                                 pal[mt][j][2], pal[mt][j][3], t2, t3);
                    }
                    LDSM_X4T(t0, t1, t2, t3, sVl + rowv * 128 + sw);
#pragma unroll
                    for (int mt = 0; mt < 2; mt++) {
                        mma16816(oacc[mt][2 * dp], pah[mt][j][0], pah[mt][j][1],
                                 pah[mt][j][2], pah[mt][j][3], t0, t1);
                        mma16816(oacc[mt][2 * dp + 1], pah[mt][j][0], pah[mt][j][1],
                                 pah[mt][j][2], pah[mt][j][3], t2, t3);
                    }
                }
        }
        __syncthreads();
    }

    float inv[2][2];
#pragma unroll
    for (int mt = 0; mt < 2; mt++)
#pragma unroll
        for (int hf = 0; hf < 2; hf++) {
            float lv = lrow[mt][hf];
            lv += __shfl_xor_sync(0xffffffffu, lv, 1);
            lv += __shfl_xor_sync(0xffffffffu, lv, 2);
            inv[mt][hf] = 1.0f / lv;
        }

#pragma unroll
    for (int mt = 0; mt < 2; mt++)
#pragma unroll
        for (int nt = 0; nt < 8; nt++) {
            int t0r = qbase + w * 32 + mt * 16 + gid;
            int col = h * HD + nt * 8 + 2 * tig;
            {
                float v0 = oacc[mt][nt][0] * inv[mt][0];
                float v1 = oacc[mt][nt][1] * inv[mt][0];
                uint32_t hp, lp;
                split_pack(v0, v1, hp, lp);
                size_t di = (size_t)(b * SEQ + t0r) * EMB + col;
                *(uint32_t*)&ath[di] = hp;
                *(uint32_t*)&atl[di] = lp;
            }
            {
                float v2 = oacc[mt][nt][2] * inv[mt][1];
                float v3 = oacc[mt][nt][3] * inv[mt][1];
                uint32_t hp, lp;
                split_pack(v2, v3, hp, lp);
                size_t di = (size_t)(b * SEQ + t0r + 8) * EMB + col;
                *(uint32_t*)&ath[di] = hp;
                *(uint32_t*)&atl[di] = lp;
            }
        }
}

// ---------------------------------------------------------------------------
extern "C" void kernel_launch(void* const* d_in, const int* in_sizes, int n_in,
                              void* d_out, int out_size)
{
    (void)in_sizes; (void)n_in; (void)out_size;
    const float* x      = (const float*)d_in[0];
    const float* W_attn = (const float*)d_in[1];
    const float* b_attn = (const float*)d_in[2];
    const float* W_proj = (const float*)d_in[3];
    const float* b_proj = (const float*)d_in[4];
    float* out = (float*)d_out;

    __nv_bfloat16 *ah, *al, *wath, *watl, *wpth, *wptl, *sh, *sl;
    cudaGetSymbolAddress((void**)&ah, g_Ah);
    cudaGetSymbolAddress((void**)&al, g_Al);
    cudaGetSymbolAddress((void**)&wath, g_WaTh);
    cudaGetSymbolAddress((void**)&watl, g_WaTl);
    cudaGetSymbolAddress((void**)&wpth, g_WpTh);
    cudaGetSymbolAddress((void**)&wptl, g_WpTl);
    cudaGetSymbolAddress((void**)&sh, g_Sh);
    cudaGetSymbolAddress((void**)&sl, g_Sl);

    cudaFuncSetAttribute(gemm_mma<0>, cudaFuncAttributeMaxDynamicSharedMemorySize, GEMM_SMEM);
    cudaFuncSetAttribute(gemm_mma<1>, cudaFuncAttributeMaxDynamicSharedMemorySize, GEMM_SMEM);
    cudaFuncSetAttribute(flash_mma,  cudaFuncAttributeMaxDynamicSharedMemorySize, FLASH_SMEM);

    {
        int n = MROWS * EMB;
        split2<<<(n + 255) / 256, 256>>>(x, ah, al, n);
    }
    transpose_split<<<dim3(QKVN / 32, EMB / 32), dim3(32, 8)>>>(W_attn, wath, watl, EMB, QKVN);
    transpose_split<<<dim3(EMB / 32, EMB / 32), dim3(32, 8)>>>(W_proj, wpth, wptl, EMB, EMB);

    // 1) QKV GEMM -> split bf16, head-major, q pre-scaled
    gemm_mma<1><<<dim3(QKVN / 96, MROWS / 128), 128, GEMM_SMEM>>>(
        ah, al, wath, watl, b_attn, nullptr, QKVN, sh, sl);

    // 2) tensor-core causal flash attention -> att split (reuses ah/al)
    flash_mma<<<dim3(SEQ / 128, NH, BATCH), 128, FLASH_SMEM>>>(sh, sl, ah, al);

    // 3) projection GEMM -> out fp32
    gemm_mma<0><<<dim3(EMB / 96, MROWS / 128), 128, GEMM_SMEM>>>(
        ah, al, wpth, wptl, b_proj, out, EMB, nullptr, nullptr);
}

// round 12
// speedup vs baseline: 3.8927x; 1.0271x over previous
#include <cuda_runtime.h>
#include <cuda_bf16.h>
#include <cstdint>
#include <math.h>

#define EMB   768
#define NH    12
#define HD    64
#define BATCH 8
#define SEQ   1024
#define MROWS (BATCH * SEQ)      // 8192
#define QKVN  (3 * EMB)          // 2304

// 0.125 (1/sqrt(64)) * log2(e): folded into Q so softmax uses ex2
#define QSCALE 0.18033688011112042f

#define TSTRIDE ((size_t)BATCH * NH * SEQ * HD)   // elems per q/k/v tensor

// ---------------------------------------------------------------------------
// Scratch (no allocations allowed)
// ---------------------------------------------------------------------------
__device__ __align__(256) __nv_bfloat16 g_Ah[(size_t)MROWS * EMB];
__device__ __align__(256) __nv_bfloat16 g_Al[(size_t)MROWS * EMB];
__device__ __align__(256) __nv_bfloat16 g_WaTh[(size_t)QKVN * EMB];
__device__ __align__(256) __nv_bfloat16 g_WaTl[(size_t)QKVN * EMB];
__device__ __align__(256) __nv_bfloat16 g_WpTh[(size_t)EMB * EMB];
__device__ __align__(256) __nv_bfloat16 g_WpTl[(size_t)EMB * EMB];
__device__ __align__(256) __nv_bfloat16 g_Sh[3 * TSTRIDE];
__device__ __align__(256) __nv_bfloat16 g_Sl[3 * TSTRIDE];

// ---------------------------------------------------------------------------
// PTX helpers (sm_80-class only; toolchain targets plain sm_103)
// ---------------------------------------------------------------------------
__device__ __forceinline__ uint32_t smem_u32(const void* p) {
    uint32_t a;
    asm("{ .reg .u64 t; cvta.to.shared.u64 t, %1; cvt.u32.u64 %0, t; }"
        : "=r"(a) : "l"(p));
    return a;
}
__device__ __forceinline__ void cp16(uint32_t dst, const void* src) {
    asm volatile("cp.async.cg.shared.global [%0], [%1], 16;"
                 :: "r"(dst), "l"(src) : "memory");
}
#define CP_COMMIT() asm volatile("cp.async.commit_group;" ::: "memory")
#define CP_WAIT(n)  asm volatile("cp.async.wait_group %0;" :: "n"(n) : "memory")

#define LDSM_X4(r0, r1, r2, r3, addr) \
    asm volatile("ldmatrix.sync.aligned.m8n8.x4.shared.b16 {%0,%1,%2,%3}, [%4];" \
                 : "=r"(r0), "=r"(r1), "=r"(r2), "=r"(r3) : "r"(addr))
#define LDSM_X4T(r0, r1, r2, r3, addr) \
    asm volatile("ldmatrix.sync.aligned.m8n8.x4.trans.shared.b16 {%0,%1,%2,%3}, [%4];" \
                 : "=r"(r0), "=r"(r1), "=r"(r2), "=r"(r3) : "r"(addr))

__device__ __forceinline__ void mma16816(float* d,
                                         uint32_t a0, uint32_t a1, uint32_t a2, uint32_t a3,
                                         uint32_t b0, uint32_t b1) {
    asm volatile("mma.sync.aligned.m16n8k16.row.col.f32.bf16.bf16.f32 "
                 "{%0,%1,%2,%3}, {%4,%5,%6,%7}, {%8,%9}, {%0,%1,%2,%3};"
                 : "+f"(d[0]), "+f"(d[1]), "+f"(d[2]), "+f"(d[3])
                 : "r"(a0), "r"(a1), "r"(a2), "r"(a3), "r"(b0), "r"(b1));
}

__device__ __forceinline__ float ex2f(float x) {
    float y;
    asm("ex2.approx.ftz.f32 %0, %1;" : "=f"(y) : "f"(x));
    return y;
}

// Fast exact split: hi = bf16x2(p1,p0) via one cvt; residual reconstructed
// with bit ops (float(bf16(p)) == bits & 0xFFFF0000 / <<16). Numerically
// identical to per-element __float2bfloat16_rn + subtract.
__device__ __forceinline__ void split_pack(float p0, float p1, uint32_t& hi, uint32_t& lo) {
    uint32_t h;
    asm("cvt.rn.bf16x2.f32 %0, %1, %2;" : "=r"(h) : "f"(p1), "f"(p0));
    float f0 = __uint_as_float(h << 16);
    float f1 = __uint_as_float(h & 0xFFFF0000u);
    float r0 = p0 - f0;
    float r1 = p1 - f1;
    uint32_t l;
    asm("cvt.rn.bf16x2.f32 %0, %1, %2;" : "=r"(l) : "f"(r1), "f"(r0));
    hi = h; lo = l;
}

// ---------------------------------------------------------------------------
// Prologue kernels
// ---------------------------------------------------------------------------
__global__ __launch_bounds__(256) void split2(const float* __restrict__ src,
                                              __nv_bfloat16* __restrict__ hi,
                                              __nv_bfloat16* __restrict__ lo, int n)
{
    int i = blockIdx.x * blockDim.x + threadIdx.x;
    if (i < n) {
        float v = src[i];
        __nv_bfloat16 h = __float2bfloat16(v);
        hi[i] = h;
        lo[i] = __float2bfloat16(v - __bfloat162float(h));
    }
}

__global__ __launch_bounds__(256) void transpose_split(
    const float* __restrict__ W, __nv_bfloat16* __restrict__ Th,
    __nv_bfloat16* __restrict__ Tl, int K, int N)
{
    __shared__ float t[32][33];
    int k0 = blockIdx.y * 32, n0 = blockIdx.x * 32;
#pragma unroll
    for (int r = 0; r < 32; r += 8) {
        int k = k0 + threadIdx.y + r;
        int n = n0 + threadIdx.x;
        t[threadIdx.y + r][threadIdx.x] = W[(size_t)k * N + n];
    }
    __syncthreads();
#pragma unroll
    for (int r = 0; r < 32; r += 8) {
        int n = n0 + threadIdx.y + r;
        int k = k0 + threadIdx.x;
        float v = t[threadIdx.x][threadIdx.y + r];
        __nv_bfloat16 h = __float2bfloat16(v);
        Th[(size_t)n * K + k] = h;
        Tl[(size_t)n * K + k] = __float2bfloat16(v - __bfloat162float(h));
    }
}

// ---------------------------------------------------------------------------
// Fused split-3 mma.sync GEMM (identical mainloop to R10 — verified 70.9% tensor)
// ---------------------------------------------------------------------------
#define AH_OFF      0
#define AL_OFF      16384
#define BH_OFF      32768
#define BL_OFF      45056
#define STAGE_BYTES 57344
#define GEMM_SMEM   (2 * STAGE_BYTES + 256)
#define NCHUNK      12

template <int MODE>
__global__ __launch_bounds__(128, 2) void gemm_mma(
    const __nv_bfloat16* __restrict__ Ah, const __nv_bfloat16* __restrict__ Al,
    const __nv_bfloat16* __restrict__ Bh, const __nv_bfloat16* __restrict__ Bl,
    const float* __restrict__ bias, float* __restrict__ C, int N,
    __nv_bfloat16* __restrict__ outh, __nv_bfloat16* __restrict__ outl)
{
    extern __shared__ char sm_raw[];
    const uint32_t base = (smem_u32(sm_raw) + 127) & ~127u;

    const int tid  = threadIdx.x;
    const int lane = tid & 31;
    const int w    = tid >> 5;
    const int wm   = w & 1;
    const int wn   = w >> 1;
    const int bn   = blockIdx.x;
    const int bm   = blockIdx.y;

    const __nv_bfloat16* Abh = Ah + (size_t)bm * 128 * EMB;
    const __nv_bfloat16* Abl = Al + (size_t)bm * 128 * EMB;
    const __nv_bfloat16* Bbh = Bh + (size_t)bn * 96 * EMB;
    const __nv_bfloat16* Bbl = Bl + (size_t)bn * 96 * EMB;

    float acc[4][6][4];
#pragma unroll
    for (int mt = 0; mt < 4; mt++)
#pragma unroll
        for (int nt = 0; nt < 6; nt++)
#pragma unroll
            for (int e = 0; e < 4; e++) acc[mt][nt][e] = 0.0f;

    auto prefetch = [&](int c) {
        const uint32_t stg = base + (uint32_t)(c & 1) * STAGE_BYTES;
        const int koff = c * 64;
#pragma unroll
        for (int j = 0; j < 8; j++) {
            int idx = tid + 128 * j;
            int row = idx >> 3;
            int s   = idx & 7;
            uint32_t off = (uint32_t)(row * 128 + ((s ^ (row & 7)) << 4));
            size_t g = (size_t)row * EMB + koff + s * 8;
            cp16(stg + AH_OFF + off, Abh + g);
            cp16(stg + AL_OFF + off, Abl + g);
        }
#pragma unroll
        for (int j = 0; j < 6; j++) {
            int idx = tid + 128 * j;
            int row = idx >> 3;
            int s   = idx & 7;
            uint32_t off = (uint32_t)(row * 128 + ((s ^ (row & 7)) << 4));
            size_t g = (size_t)row * EMB + koff + s * 8;
            cp16(stg + BH_OFF + off, Bbh + g);
            cp16(stg + BL_OFF + off, Bbl + g);
        }
    };

    prefetch(0);
    CP_COMMIT();

    const int qm = lane >> 3;
    const int r8 = lane & 7;

    for (int c = 0; c < NCHUNK; c++) {
        const uint32_t stg = base + (uint32_t)(c & 1) * STAGE_BYTES;

        if (c + 1 < NCHUNK) {
            prefetch(c + 1);
            CP_COMMIT();
            CP_WAIT(1);
        } else {
            CP_WAIT(0);
        }
        __syncthreads();

#pragma unroll
        for (int u = 0; u < 2; u++) {
            uint32_t ah[4][2][4], al[4][2][4];
#pragma unroll
            for (int mt = 0; mt < 4; mt++)
#pragma unroll
                for (int ks = 0; ks < 2; ks++) {
                    int arow = wm * 64 + mt * 16 + (qm & 1) * 8 + r8;
                    int aseg = (2 * u + ks) * 2 + (qm >> 1);
                    uint32_t sw = arow * 128 + ((aseg ^ (arow & 7)) << 4);
                    LDSM_X4(ah[mt][ks][0], ah[mt][ks][1], ah[mt][ks][2], ah[mt][ks][3],
                            stg + AH_OFF + sw);
                    LDSM_X4(al[mt][ks][0], al[mt][ks][1], al[mt][ks][2], al[mt][ks][3],
                            stg + AL_OFF + sw);
                }
#pragma unroll
            for (int nt = 0; nt < 6; nt++) {
                int brow = wn * 48 + nt * 8 + r8;
                int bseg = u * 4 + qm;
                uint32_t bsw = brow * 128 + ((bseg ^ (brow & 7)) << 4);
                uint32_t t0, t1, t2, t3;
                LDSM_X4(t0, t1, t2, t3, stg + BH_OFF + bsw);
#pragma unroll
                for (int mt = 0; mt < 4; mt++) {
                    mma16816(acc[mt][nt], ah[mt][0][0], ah[mt][0][1],
                             ah[mt][0][2], ah[mt][0][3], t0, t1);
                    mma16816(acc[mt][nt], ah[mt][1][0], ah[mt][1][1],
                             ah[mt][1][2], ah[mt][1][3], t2, t3);
                    mma16816(acc[mt][nt], al[mt][0][0], al[mt][0][1],
                             al[mt][0][2], al[mt][0][3], t0, t1);
                    mma16816(acc[mt][nt], al[mt][1][0], al[mt][1][1],
                             al[mt][1][2], al[mt][1][3], t2, t3);
                }
                LDSM_X4(t0, t1, t2, t3, stg + BL_OFF + bsw);
#pragma unroll
                for (int mt = 0; mt < 4; mt++) {
                    mma16816(acc[mt][nt], ah[mt][0][0], ah[mt][0][1],
                             ah[mt][0][2], ah[mt][0][3], t0, t1);
                    mma16816(acc[mt][nt], ah[mt][1][0], ah[mt][1][1],
                             ah[mt][1][2], ah[mt][1][3], t2, t3);
                }
            }
        }
        __syncthreads();
    }

    // ---- epilogue ----
    const int row0 = bm * 128 + wm * 64 + (lane >> 2);
    const int col0 = bn * 96 + wn * 48 + 2 * (lane & 3);
#pragma unroll
    for (int mt = 0; mt < 4; mt++)
#pragma unroll
        for (int nt = 0; nt < 6; nt++) {
            int rr = row0 + mt * 16;
            int cc = col0 + nt * 8;
            float b0 = bias[cc], b1 = bias[cc + 1];
            float v0 = acc[mt][nt][0] + b0, v1 = acc[mt][nt][1] + b1;
            float v2 = acc[mt][nt][2] + b0, v3 = acc[mt][nt][3] + b1;
            if (MODE == 0) {
                *(float2*)&C[(size_t)rr * N + cc]       = make_float2(v0, v1);
                *(float2*)&C[(size_t)(rr + 8) * N + cc] = make_float2(v2, v3);
            } else {
                int tensor = cc / 768;
                int within = cc % 768;
                int hh = within >> 6, dd = within & 63;
                if (tensor == 0) { v0 *= QSCALE; v1 *= QSCALE; v2 *= QSCALE; v3 *= QSCALE; }
                uint32_t h01, l01, h23, l23;
                split_pack(v0, v1, h01, l01);
                split_pack(v2, v3, h23, l23);
                {
                    int bb = rr >> 10, t = rr & 1023;
                    size_t di = (size_t)tensor * TSTRIDE +
                                (size_t)(bb * NH + hh) * (SEQ * HD) + (size_t)t * HD + dd;
                    *(uint32_t*)&outh[di] = h01;
                    *(uint32_t*)&outl[di] = l01;
                }
                {
                    int rr2 = rr + 8;
                    int bb = rr2 >> 10, t = rr2 & 1023;
                    size_t di = (size_t)tensor * TSTRIDE +
                                (size_t)(bb * NH + hh) * (SEQ * HD) + (size_t)t * HD + dd;
                    *(uint32_t*)&outh[di] = h23;
                    *(uint32_t*)&outl[di] = l23;
                }
            }
        }
}

// ---------------------------------------------------------------------------
// Tensor-core causal flash attention — 3-stage KV ring reusing Q smem.
// Slot k = base + (kt%3)*FSTAGE; Q lives in slot 2 until its fragments are
// register-resident, then slot 2 joins the ring (first used by KV tile 2).
// One __syncthreads per tile; cp.async prefetch 2 tiles deep.
// ---------------------------------------------------------------------------
#define FT_BYTES  8192
#define FSTAGE    (4 * FT_BYTES)              // 32 KB: Kh,Kl,Vh,Vl
#define FLASH_SMEM (3 * FSTAGE + 1024)

__device__ __forceinline__ void prefetch_kv(uint32_t dst,
    const __nv_bfloat16* __restrict__ Kh, const __nv_bfloat16* __restrict__ Kl,
    const __nv_bfloat16* __restrict__ Vh, const __nv_bfloat16* __restrict__ Vl,
    int kt, int tid)
{
    const __nv_bfloat16* srcs[4] = {Kh, Kl, Vh, Vl};
#pragma unroll
    for (int t4 = 0; t4 < 4; t4++) {
        const __nv_bfloat16* src = srcs[t4] + (size_t)(kt * 64) * HD;
#pragma unroll
        for (int jj = 0; jj < 4; jj++) {
            int idx = tid + 128 * jj;
            int row = idx >> 3;
            int s   = idx & 7;
            cp16(dst + t4 * FT_BYTES + row * 128 + ((s ^ (row & 7)) << 4),
                 src + (size_t)row * HD + s * 8);
        }
    }
}

__global__ __launch_bounds__(128, 2) void flash_mma(
    const __nv_bfloat16* __restrict__ Sh, const __nv_bfloat16* __restrict__ Sl,
    __nv_bfloat16* __restrict__ ath, __nv_bfloat16* __restrict__ atl)
{
    extern __shared__ char sm_raw[];
    const uint32_t base = (smem_u32(sm_raw) + 1023) & ~1023u;

    const int tid  = threadIdx.x;
    const int lane = tid & 31;
    const int w    = tid >> 5;
    const int qm   = lane >> 3;
    const int r8   = lane & 7;
    const int tig  = lane & 3;
    const int gid  = lane >> 2;

    const int qt = (SEQ / 128 - 1) - blockIdx.x;   // heavy tiles first
    const int h  = blockIdx.y;
    const int b  = blockIdx.z;
    const int bh = b * NH + h;
    const int qbase = qt * 128;

    const size_t hb = (size_t)bh * (SEQ * HD);
    const __nv_bfloat16* Qhp = Sh + hb;
    const __nv_bfloat16* Qlp = Sl + hb;
    const __nv_bfloat16* Khp = Sh + TSTRIDE + hb;
    const __nv_bfloat16* Klp = Sl + TSTRIDE + hb;
    const __nv_bfloat16* Vhp = Sh + 2 * TSTRIDE + hb;
    const __nv_bfloat16* Vlp = Sl + 2 * TSTRIDE + hb;

    const int lastkt = 2 * qt + 1;                 // >= 1 always

    // Q parked in slot 2 (QH at +0, QL at +16K of the slot)
    const uint32_t QH_S = base + 2 * FSTAGE;
    const uint32_t QL_S = QH_S + 16384;

    // --- prologue: G_Q, G_0, G_1 ---
    {
        const __nv_bfloat16* qs[2] = {Qhp, Qlp};
        uint32_t qd[2] = {QH_S, QL_S};
#pragma unroll
        for (int t2 = 0; t2 < 2; t2++)
#pragma unroll
            for (int jj = 0; jj < 8; jj++) {
                int idx = tid + 128 * jj;
                int row = idx >> 3;
                int s   = idx & 7;
                cp16(qd[t2] + row * 128 + ((s ^ (row & 7)) << 4),
                     qs[t2] + (size_t)(qbase + row) * HD + s * 8);
            }
        CP_COMMIT();                                   // G_Q
        prefetch_kv(base, Khp, Klp, Vhp, Vlp, 0, tid);
        CP_COMMIT();                                   // G_0
        prefetch_kv(base + FSTAGE, Khp, Klp, Vhp, Vlp, 1, tid);
        CP_COMMIT();                                   // G_1
    }

    // Q fragments -> registers (slot 2 then joins the ring)
    uint32_t qfh[2][4][4], qfl[2][4][4];
    CP_WAIT(2);                                        // G_Q complete
    __syncthreads();
#pragma unroll
    for (int mt = 0; mt < 2; mt++)
#pragma unroll
        for (int kk = 0; kk < 4; kk++) {
            int arow = w * 32 + mt * 16 + (qm & 1) * 8 + r8;
            int aseg = kk * 2 + (qm >> 1);
            uint32_t sw = ((aseg ^ (arow & 7)) << 4);
            LDSM_X4(qfh[mt][kk][0], qfh[mt][kk][1], qfh[mt][kk][2], qfh[mt][kk][3],
                    QH_S + arow * 128 + sw);
            LDSM_X4(qfl[mt][kk][0], qfl[mt][kk][1], qfl[mt][kk][2], qfl[mt][kk][3],
                    QL_S + arow * 128 + sw);
        }
    __syncthreads();                                   // all Q frags read

    float oacc[2][8][4];
#pragma unroll
    for (int mt = 0; mt < 2; mt++)
#pragma unroll
        for (int nt = 0; nt < 8; nt++)
#pragma unroll
            for (int e = 0; e < 4; e++) oacc[mt][nt][e] = 0.0f;
    float mrow[2][2], lrow[2][2];
#pragma unroll
    for (int mt = 0; mt < 2; mt++)
#pragma unroll
        for (int hf = 0; hf < 2; hf++) { mrow[mt][hf] = -1e30f; lrow[mt][hf] = 0.0f; }

    const int wrowmax = qbase + w * 32 + 31;

    for (int kt = 0; kt <= lastkt; kt++) {
        CP_WAIT(1);            // G_kt (and older) complete per-thread
        __syncthreads();       // cross-thread visibility + skew bound
        if (kt + 2 <= lastkt)  // prefetch into slot (kt+2)%3 == (kt-1)%3 (freed by barrier)
            prefetch_kv(base + (uint32_t)((kt + 2) % 3) * FSTAGE,
                        Khp, Klp, Vhp, Vlp, kt + 2, tid);
        CP_COMMIT();           // unconditional: keeps group accounting uniform

        const uint32_t SB = base + (uint32_t)(kt % 3) * FSTAGE;

        if (kt * 64 <= wrowmax) {
            const uint32_t sKh = SB;
            const uint32_t sKl = SB + FT_BYTES;
            const uint32_t sVh = SB + 2 * FT_BYTES;
            const uint32_t sVl = SB + 3 * FT_BYTES;

            float sacc[2][8][4];
#pragma unroll
            for (int mt = 0; mt < 2; mt++)
#pragma unroll
                for (int nt = 0; nt < 8; nt++)
#pragma unroll
                    for (int e = 0; e < 4; e++) sacc[mt][nt][e] = 0.0f;

#pragma unroll
            for (int u = 0; u < 2; u++)
#pragma unroll
                for (int nt = 0; nt < 8; nt++) {
                    int brow = nt * 8 + r8;
                    int bseg = u * 4 + qm;
                    uint32_t sw = ((bseg ^ (brow & 7)) << 4);
                    uint32_t t0, t1, t2, t3;
                    LDSM_X4(t0, t1, t2, t3, sKh + brow * 128 + sw);
#pragma unroll
                    for (int mt = 0; mt < 2; mt++) {
                        mma16816(sacc[mt][nt], qfh[mt][2 * u][0], qfh[mt][2 * u][1],
                                 qfh[mt][2 * u][2], qfh[mt][2 * u][3], t0, t1);
                        mma16816(sacc[mt][nt], qfh[mt][2 * u + 1][0], qfh[mt][2 * u + 1][1],
                                 qfh[mt][2 * u + 1][2], qfh[mt][2 * u + 1][3], t2, t3);
                        mma16816(sacc[mt][nt], qfl[mt][2 * u][0], qfl[mt][2 * u][1],
                                 qfl[mt][2 * u][2], qfl[mt][2 * u][3], t0, t1);
                        mma16816(sacc[mt][nt], qfl[mt][2 * u + 1][0], qfl[mt][2 * u + 1][1],
                                 qfl[mt][2 * u + 1][2], qfl[mt][2 * u + 1][3], t2, t3);
                    }
                    LDSM_X4(t0, t1, t2, t3, sKl + brow * 128 + sw);
#pragma unroll
                    for (int mt = 0; mt < 2; mt++) {
                        mma16816(sacc[mt][nt], qfh[mt][2 * u][0], qfh[mt][2 * u][1],
                                 qfh[mt][2 * u][2], qfh[mt][2 * u][3], t0, t1);
                        mma16816(sacc[mt][nt], qfh[mt][2 * u + 1][0], qfh[mt][2 * u + 1][1],
                                 qfh[mt][2 * u + 1][2], qfh[mt][2 * u + 1][3], t2, t3);
                    }
                }

            if (kt >= 2 * qt) {
                int qr0 = qbase + w * 32 + gid;
                int kc0 = kt * 64 + 2 * tig;
#pragma unroll
                for (int mt = 0; mt < 2; mt++)
#pragma unroll
                    for (int nt = 0; nt < 8; nt++)
#pragma unroll
                        for (int e = 0; e < 4; e++) {
                            int qr = qr0 + mt * 16 + (e >> 1) * 8;
                            int kc = kc0 + nt * 8 + (e & 1);
                            if (kc > qr) sacc[mt][nt][e] = -1e30f;
                        }
            }

            float corr[2][2], nm[2][2];
#pragma unroll
            for (int mt = 0; mt < 2; mt++)
#pragma unroll
                for (int hf = 0; hf < 2; hf++) {
                    float tm = -1e30f;
#pragma unroll
                    for (int nt = 0; nt < 8; nt++) {
                        tm = fmaxf(tm, sacc[mt][nt][2 * hf]);
                        tm = fmaxf(tm, sacc[mt][nt][2 * hf + 1]);
                    }
                    tm = fmaxf(tm, __shfl_xor_sync(0xffffffffu, tm, 1));
                    tm = fmaxf(tm, __shfl_xor_sync(0xffffffffu, tm, 2));
                    float n = fmaxf(mrow[mt][hf], tm);
                    corr[mt][hf] = ex2f(mrow[mt][hf] - n);
                    nm[mt][hf] = n;
                    mrow[mt][hf] = n;
                }

#pragma unroll
            for (int mt = 0; mt < 2; mt++)
#pragma unroll
                for (int hf = 0; hf < 2; hf++) {
                    float ps = 0.0f;
#pragma unroll
                    for (int nt = 0; nt < 8; nt++) {
                        float p0 = ex2f(sacc[mt][nt][2 * hf]     - nm[mt][hf]);
                        float p1 = ex2f(sacc[mt][nt][2 * hf + 1] - nm[mt][hf]);
                        sacc[mt][nt][2 * hf]     = p0;
                        sacc[mt][nt][2 * hf + 1] = p1;
                        ps += p0 + p1;
                    }
                    lrow[mt][hf] = lrow[mt][hf] * corr[mt][hf] + ps;
                }

#pragma unroll
            for (int mt = 0; mt < 2; mt++)
#pragma unroll
                for (int nt = 0; nt < 8; nt++) {
                    oacc[mt][nt][0] *= corr[mt][0];
                    oacc[mt][nt][1] *= corr[mt][0];
                    oacc[mt][nt][2] *= corr[mt][1];
                    oacc[mt][nt][3] *= corr[mt][1];
                }

            uint32_t pah[2][4][4], pal[2][4][4];
#pragma unroll
            for (int mt = 0; mt < 2; mt++)
#pragma unroll
                for (int j = 0; j < 4; j++) {
                    split_pack(sacc[mt][2 * j][0],     sacc[mt][2 * j][1],
                               pah[mt][j][0], pal[mt][j][0]);
                    split_pack(sacc[mt][2 * j][2],     sacc[mt][2 * j][3],
                               pah[mt][j][1], pal[mt][j][1]);
                    split_pack(sacc[mt][2 * j + 1][0], sacc[mt][2 * j + 1][1],
                               pah[mt][j][2], pal[mt][j][2]);
                    split_pack(sacc[mt][2 * j + 1][2], sacc[mt][2 * j + 1][3],
                               pah[mt][j][3], pal[mt][j][3]);
                }

#pragma unroll
            for (int j = 0; j < 4; j++)
#pragma unroll
                for (int dp = 0; dp < 4; dp++) {
                    int rowv = j * 16 + (lane & 15);
                    int segv = dp * 2 + (lane >> 4);
                    uint32_t sw = ((segv ^ (rowv & 7)) << 4);
                    uint32_t t0, t1, t2, t3;
                    LDSM_X4T(t0, t1, t2, t3, sVh + rowv * 128 + sw);
#pragma unroll
                    for (int mt = 0; mt < 2; mt++) {
                        mma16816(oacc[mt][2 * dp], pah[mt][j][0], pah[mt][j][1],
                                 pah[mt][j][2], pah[mt][j][3], t0, t1);
                        mma16816(oacc[mt][2 * dp + 1], pah[mt][j][0], pah[mt][j][1],
                                 pah[mt][j][2], pah[mt][j][3], t2, t3);
                        mma16816(oacc[mt][2 * dp], pal[mt][j][0], pal[mt][j][1],
                                 pal[mt][j][2], pal[mt][j][3], t0, t1);
                        mma16816(oacc[mt][2 * dp + 1], pal[mt][j][0], pal[mt][j][1],
                                 pal[mt][j][2], pal[mt][j][3], t2, t3);
                    }
                    LDSM_X4T(t0, t1, t2, t3, sVl + rowv * 128 + sw);
#pragma unroll
                    for (int mt = 0; mt < 2; mt++) {
                        mma16816(oacc[mt][2 * dp], pah[mt][j][0], pah[mt][j][1],
                                 pah[mt][j][2], pah[mt][j][3], t0, t1);
                        mma16816(oacc[mt][2 * dp + 1], pah[mt][j][0], pah[mt][j][1],
                                 pah[mt][j][2], pah[mt][j][3], t2, t3);
                    }
                }
        }
    }

    float inv[2][2];
#pragma unroll
    for (int mt = 0; mt < 2; mt++)
#pragma unroll
        for (int hf = 0; hf < 2; hf++) {
            float lv = lrow[mt][hf];
            lv += __shfl_xor_sync(0xffffffffu, lv, 1);
            lv += __shfl_xor_sync(0xffffffffu, lv, 2);
            inv[mt][hf] = 1.0f / lv;
        }

#pragma unroll
    for (int mt = 0; mt < 2; mt++)
#pragma unroll
        for (int nt = 0; nt < 8; nt++) {
            int t0r = qbase + w * 32 + mt * 16 + gid;
            int col = h * HD + nt * 8 + 2 * tig;
            {
                float v0 = oacc[mt][nt][0] * inv[mt][0];
                float v1 = oacc[mt][nt][1] * inv[mt][0];
                uint32_t hp, lp;
                split_pack(v0, v1, hp, lp);
                size_t di = (size_t)(b * SEQ + t0r) * EMB + col;
                *(uint32_t*)&ath[di] = hp;
                *(uint32_t*)&atl[di] = lp;
            }
            {
                float v2 = oacc[mt][nt][2] * inv[mt][1];
                float v3 = oacc[mt][nt][3] * inv[mt][1];
                uint32_t hp, lp;
                split_pack(v2, v3, hp, lp);
                size_t di = (size_t)(b * SEQ + t0r + 8) * EMB + col;
                *(uint32_t*)&ath[di] = hp;
                *(uint32_t*)&atl[di] = lp;
            }
        }
}

// ---------------------------------------------------------------------------
extern "C" void kernel_launch(void* const* d_in, const int* in_sizes, int n_in,
                              void* d_out, int out_size)
{
    (void)in_sizes; (void)n_in; (void)out_size;
    const float* x      = (const float*)d_in[0];
    const float* W_attn = (const float*)d_in[1];
    const float* b_attn = (const float*)d_in[2];
    const float* W_proj = (const float*)d_in[3];
    const float* b_proj = (const float*)d_in[4];
    float* out = (float*)d_out;

    __nv_bfloat16 *ah, *al, *wath, *watl, *wpth, *wptl, *sh, *sl;
    cudaGetSymbolAddress((void**)&ah, g_Ah);
    cudaGetSymbolAddress((void**)&al, g_Al);
    cudaGetSymbolAddress((void**)&wath, g_WaTh);
    cudaGetSymbolAddress((void**)&watl, g_WaTl);
    cudaGetSymbolAddress((void**)&wpth, g_WpTh);
    cudaGetSymbolAddress((void**)&wptl, g_WpTl);
    cudaGetSymbolAddress((void**)&sh, g_Sh);
    cudaGetSymbolAddress((void**)&sl, g_Sl);

    cudaFuncSetAttribute(gemm_mma<0>, cudaFuncAttributeMaxDynamicSharedMemorySize, GEMM_SMEM);
    cudaFuncSetAttribute(gemm_mma<1>, cudaFuncAttributeMaxDynamicSharedMemorySize, GEMM_SMEM);
    cudaFuncSetAttribute(flash_mma,  cudaFuncAttributeMaxDynamicSharedMemorySize, FLASH_SMEM);

    {
        int n = MROWS * EMB;
        split2<<<(n + 255) / 256, 256>>>(x, ah, al, n);
    }
    transpose_split<<<dim3(QKVN / 32, EMB / 32), dim3(32, 8)>>>(W_attn, wath, watl, EMB, QKVN);
    transpose_split<<<dim3(EMB / 32, EMB / 32), dim3(32, 8)>>>(W_proj, wpth, wptl, EMB, EMB);

    // 1) QKV GEMM -> split bf16, head-major, q pre-scaled
    gemm_mma<1><<<dim3(QKVN / 96, MROWS / 128), 128, GEMM_SMEM>>>(
        ah, al, wath, watl, b_attn, nullptr, QKVN, sh, sl);

    // 2) tensor-core causal flash attention -> att split (reuses ah/al)
    flash_mma<<<dim3(SEQ / 128, NH, BATCH), 128, FLASH_SMEM>>>(sh, sl, ah, al);

    // 3) projection GEMM -> out fp32
    gemm_mma<0><<<dim3(EMB / 96, MROWS / 128), 128, GEMM_SMEM>>>(
        ah, al, wpth, wptl, b_proj, out, EMB, nullptr, nullptr);
}